// round 3
// baseline (speedup 1.0000x reference)
#include <cuda_runtime.h>
#include <stdint.h>
#include <math.h>

#define T_TOK 4096
#define DIM   2048
#define INTER 1024
#define NEXP  8
#define NE    9      // 8 routed + 1 shared pseudo-expert
#define BK    16
#define SA    20     // smem row stride (floats): 16 + 4 pad

// ---------------- scratch (device globals; no allocation allowed) ----------------
__device__ float g_hidden [(size_t)NE * T_TOK * INTER];  // [e*T+slot][INTER] post-SwiGLU (tf32-rounded)
__device__ float g_pairout[(size_t)NE * T_TOK * DIM];    // [e*T+slot][DIM] weighted expert out
__device__ float g_xtf    [(size_t)T_TOK * DIM];         // tf32-rounded activations
__device__ float g_w1c [(size_t)NEXP * INTER * DIM];
__device__ float g_w3c [(size_t)NEXP * INTER * DIM];
__device__ float g_w2c [(size_t)NEXP * DIM * INTER];
__device__ float g_ws1c[(size_t)INTER * DIM];
__device__ float g_ws3c[(size_t)INTER * DIM];
__device__ float g_ws2c[(size_t)DIM * INTER];
__device__ int   g_pair_tok[NE * T_TOK];
__device__ float g_pair_w [NE * T_TOK];
__device__ int   g_tok_rows[T_TOK * 2];                  // token -> its 2 routed pair rows
__device__ int   g_cnt[NE];

// ---------------- PTX helpers ----------------
__device__ __forceinline__ uint32_t smem_u32(const void* p) {
    return (uint32_t)__cvta_generic_to_shared(p);
}
__device__ __forceinline__ void cp16(uint32_t dst, const float* src, bool valid) {
    int sz = valid ? 16 : 0;
    asm volatile("cp.async.cg.shared.global [%0], [%1], 16, %2;\n"
                 :: "r"(dst), "l"(src), "r"(sz));
}
#define CP_COMMIT() asm volatile("cp.async.commit_group;\n")
#define CP_WAIT1()  asm volatile("cp.async.wait_group 1;\n")
#define CP_WAIT0()  asm volatile("cp.async.wait_group 0;\n")

__device__ __forceinline__ uint32_t f2tf(float f) {
    uint32_t u; asm("cvt.rna.tf32.f32 %0, %1;" : "=r"(u) : "f"(f)); return u;
}
__device__ __forceinline__ float tfr(float f) {          // round-to-nearest tf32, as float
    return __uint_as_float(f2tf(f));
}
__device__ __forceinline__ void mma_tf32(float* c, const uint32_t* a, const uint32_t* b) {
    asm volatile("mma.sync.aligned.m16n8k8.row.col.f32.tf32.tf32.f32 "
        "{%0,%1,%2,%3}, {%4,%5,%6,%7}, {%8,%9}, {%0,%1,%2,%3};\n"
        : "+f"(c[0]), "+f"(c[1]), "+f"(c[2]), "+f"(c[3])
        : "r"(a[0]), "r"(a[1]), "r"(a[2]), "r"(a[3]), "r"(b[0]), "r"(b[1]));
}

// ---------------- kernel 0: reset counters ----------------
__global__ void init_kernel() {
    int i = threadIdx.x;
    if (i < NE) g_cnt[i] = (i == NEXP) ? T_TOK : 0;
}

// ---------------- weight pre-round kernel (f32 -> tf32-rounded f32) ------------
__global__ void convert_kernel(const float4* __restrict__ src,
                               float4* __restrict__ dst, int n4) {
    int stride = gridDim.x * blockDim.x;
    for (int i = blockIdx.x * blockDim.x + threadIdx.x; i < n4; i += stride) {
        float4 v = src[i];
        v.x = tfr(v.x); v.y = tfr(v.y); v.z = tfr(v.z); v.w = tfr(v.w);
        dst[i] = v;
    }
}

// ---------------- kernel 1: gate (softmax + top2 + list build) + x rounding ----
__global__ void gate_kernel(const float* __restrict__ x,
                            const float* __restrict__ gw) {
    int t = blockIdx.x;
    const float* xr = x + (size_t)t * DIM;
    float* xo = g_xtf + (size_t)t * DIM;

    float acc[NEXP];
#pragma unroll
    for (int e = 0; e < NEXP; e++) acc[e] = 0.f;
    for (int d = threadIdx.x; d < DIM; d += 256) {
        float xv = xr[d];
        xo[d] = tfr(xv);
#pragma unroll
        for (int e = 0; e < NEXP; e++) acc[e] += xv * gw[e * DIM + d];
    }
#pragma unroll
    for (int off = 16; off > 0; off >>= 1) {
#pragma unroll
        for (int e = 0; e < NEXP; e++)
            acc[e] += __shfl_down_sync(0xffffffffu, acc[e], off);
    }
    __shared__ float sw[8][NEXP];
    int warp = threadIdx.x >> 5, lane = threadIdx.x & 31;
    if (lane == 0) {
#pragma unroll
        for (int e = 0; e < NEXP; e++) sw[warp][e] = acc[e];
    }
    __syncthreads();
    if (threadIdx.x == 0) {
        float lg[NEXP];
#pragma unroll
        for (int e = 0; e < NEXP; e++) {
            float s = 0.f;
#pragma unroll
            for (int w = 0; w < 8; w++) s += sw[w][e];
            lg[e] = s;
        }
        float mx = lg[0];
#pragma unroll
        for (int e = 1; e < NEXP; e++) mx = fmaxf(mx, lg[e]);
        float p[NEXP]; float sum = 0.f;
#pragma unroll
        for (int e = 0; e < NEXP; e++) { p[e] = expf(lg[e] - mx); sum += p[e]; }
        float inv = 1.f / sum;
#pragma unroll
        for (int e = 0; e < NEXP; e++) p[e] *= inv;
        int i1 = 0;
#pragma unroll
        for (int e = 1; e < NEXP; e++) if (p[e] > p[i1]) i1 = e;
        int i2 = (i1 == 0) ? 1 : 0;
#pragma unroll
        for (int e = 0; e < NEXP; e++) if (e != i1 && p[e] > p[i2]) i2 = e;

        int s1 = atomicAdd(&g_cnt[i1], 1);
        g_pair_tok[i1 * T_TOK + s1] = t;
        g_pair_w [i1 * T_TOK + s1] = p[i1];
        int s2 = atomicAdd(&g_cnt[i2], 1);
        g_pair_tok[i2 * T_TOK + s2] = t;
        g_pair_w [i2 * T_TOK + s2] = p[i2];
        g_tok_rows[2 * t]     = i1 * T_TOK + s1;
        g_tok_rows[2 * t + 1] = i2 * T_TOK + s2;
        g_pair_tok[NEXP * T_TOK + t] = t;
        g_pair_w [NEXP * T_TOK + t] = 1.0f;
    }
}

// ---------------- kernel 2: fused up-proj, TF32 mma, H = silu(XW1^T)*(XW3^T) ----
#define UP_BM 128
#define UP_BN 64

__global__ __launch_bounds__(256, 2)
void up_kernel() {
    __shared__ float As [2][UP_BM * SA];
    __shared__ float B1s[2][UP_BN * SA];
    __shared__ float B3s[2][UP_BN * SA];

    int e = blockIdx.z;
    int cnt = g_cnt[e];
    int m0 = blockIdx.y * UP_BM;
    if (m0 >= cnt) return;
    int n0 = blockIdx.x * UP_BN;

    const float* B1 = (e < NEXP) ? g_w1c + (size_t)e * INTER * DIM : g_ws1c;
    const float* B3 = (e < NEXP) ? g_w3c + (size_t)e * INTER * DIM : g_ws3c;

    int tid = threadIdx.x;
    int ar0 = tid >> 2, ar1 = ar0 + 64;
    int ak  = (tid & 3) * 4;
    bool v0 = (m0 + ar0 < cnt), v1 = (m0 + ar1 < cnt);
    int t0 = v0 ? g_pair_tok[e * T_TOK + m0 + ar0] : 0;
    int t1 = v1 ? g_pair_tok[e * T_TOK + m0 + ar1] : 0;
    const float* asrc0 = g_xtf + (size_t)t0 * DIM + ak;
    const float* asrc1 = g_xtf + (size_t)t1 * DIM + ak;
    int br = tid >> 2, bk = (tid & 3) * 4;
    const float* b1src = B1 + (size_t)(n0 + br) * DIM + bk;
    const float* b3src = B3 + (size_t)(n0 + br) * DIM + bk;

    uint32_t dA0[2], dA1[2], dB1[2], dB3[2];
#pragma unroll
    for (int b = 0; b < 2; b++) {
        dA0[b] = smem_u32(&As [b][ar0 * SA + ak]);
        dA1[b] = smem_u32(&As [b][ar1 * SA + ak]);
        dB1[b] = smem_u32(&B1s[b][br  * SA + bk]);
        dB3[b] = smem_u32(&B3s[b][br  * SA + bk]);
    }

    int w = tid >> 5, lane = tid & 31;
    int g = lane >> 2, tg = lane & 3;
    int mw = (w & 3) * 32, nw = (w >> 2) * 32;

    float acc1[2][4][4], acc3[2][4][4];
#pragma unroll
    for (int mi = 0; mi < 2; mi++)
#pragma unroll
        for (int ni = 0; ni < 4; ni++)
#pragma unroll
            for (int q = 0; q < 4; q++) { acc1[mi][ni][q] = 0.f; acc3[mi][ni][q] = 0.f; }

    cp16(dA0[0], asrc0, v0); cp16(dA1[0], asrc1, v1);
    cp16(dB1[0], b1src, true); cp16(dB3[0], b3src, true);
    CP_COMMIT();

    int buf = 0;
    for (int k0 = 0; k0 < DIM; k0 += BK) {
        if (k0 + BK < DIM) {
            int nb = buf ^ 1, kn = k0 + BK;
            cp16(dA0[nb], asrc0 + kn, v0); cp16(dA1[nb], asrc1 + kn, v1);
            cp16(dB1[nb], b1src + kn, true); cp16(dB3[nb], b3src + kn, true);
            CP_COMMIT();
            CP_WAIT1();
        } else {
            CP_WAIT0();
        }
        __syncthreads();
#pragma unroll
        for (int ks = 0; ks < 2; ks++) {
            int kb = ks * 8;
            uint32_t afr[2][4];
#pragma unroll
            for (int mi = 0; mi < 2; mi++) {
                const float* ab = &As[buf][(mw + mi * 16 + g) * SA + kb + tg];
                afr[mi][0] = __float_as_uint(ab[0]);
                afr[mi][1] = __float_as_uint(ab[8 * SA]);
                afr[mi][2] = __float_as_uint(ab[4]);
                afr[mi][3] = __float_as_uint(ab[8 * SA + 4]);
            }
#pragma unroll
            for (int ni = 0; ni < 4; ni++) {
                const float* b1b = &B1s[buf][(nw + ni * 8 + g) * SA + kb + tg];
                const float* b3b = &B3s[buf][(nw + ni * 8 + g) * SA + kb + tg];
                uint32_t b1f[2] = { __float_as_uint(b1b[0]), __float_as_uint(b1b[4]) };
                uint32_t b3f[2] = { __float_as_uint(b3b[0]), __float_as_uint(b3b[4]) };
#pragma unroll
                for (int mi = 0; mi < 2; mi++) {
                    mma_tf32(acc1[mi][ni], afr[mi], b1f);
                    mma_tf32(acc3[mi][ni], afr[mi], b3f);
                }
            }
        }
        __syncthreads();
        buf ^= 1;
    }

    // epilogue: silu(h1)*h3 -> g_hidden (tf32-rounded for the down GEMM)
#pragma unroll
    for (int mi = 0; mi < 2; mi++)
#pragma unroll
        for (int h = 0; h < 2; h++) {
            int slot = m0 + mw + mi * 16 + g + h * 8;
            if (slot < cnt) {
                size_t base = ((size_t)e * T_TOK + slot) * INTER + n0 + nw;
#pragma unroll
                for (int ni = 0; ni < 4; ni++) {
                    float h1a = acc1[mi][ni][h * 2], h1b = acc1[mi][ni][h * 2 + 1];
                    float h3a = acc3[mi][ni][h * 2], h3b = acc3[mi][ni][h * 2 + 1];
                    float2 st;
                    st.x = tfr((h1a / (1.f + __expf(-h1a))) * h3a);
                    st.y = tfr((h1b / (1.f + __expf(-h1b))) * h3b);
                    *(float2*)&g_hidden[base + ni * 8 + tg * 2] = st;
                }
            }
        }
}

// ---------------- kernel 3: down-proj, TF32 mma, weighted store (no atomics) ----
#define DN_BM 128
#define DN_BN 128

__global__ __launch_bounds__(256, 2)
void down_kernel() {
    __shared__ float As[2][DN_BM * SA];
    __shared__ float Bs[2][DN_BN * SA];

    int e = blockIdx.z;
    int cnt = g_cnt[e];
    int m0 = blockIdx.y * DN_BM;
    if (m0 >= cnt) return;
    int n0 = blockIdx.x * DN_BN;

    const float* B = (e < NEXP) ? g_w2c + (size_t)e * DIM * INTER : g_ws2c;

    int tid = threadIdx.x;
    int ar0 = tid >> 2, ar1 = ar0 + 64;
    int ak  = (tid & 3) * 4;
    bool v0 = (m0 + ar0 < cnt), v1 = (m0 + ar1 < cnt);
    const float* asrc0 = g_hidden + ((size_t)e * T_TOK + (v0 ? m0 + ar0 : 0)) * INTER + ak;
    const float* asrc1 = g_hidden + ((size_t)e * T_TOK + (v1 ? m0 + ar1 : 0)) * INTER + ak;
    const float* bsrc0 = B + (size_t)(n0 + ar0) * INTER + ak;
    const float* bsrc1 = B + (size_t)(n0 + ar1) * INTER + ak;

    uint32_t dA0[2], dA1[2], dB0[2], dB1[2];
#pragma unroll
    for (int b = 0; b < 2; b++) {
        dA0[b] = smem_u32(&As[b][ar0 * SA + ak]);
        dA1[b] = smem_u32(&As[b][ar1 * SA + ak]);
        dB0[b] = smem_u32(&Bs[b][ar0 * SA + ak]);
        dB1[b] = smem_u32(&Bs[b][ar1 * SA + ak]);
    }

    int w = tid >> 5, lane = tid & 31;
    int g = lane >> 2, tg = lane & 3;
    int mw = (w & 3) * 32, nw = (w >> 2) * 64;

    float acc[2][8][4];
#pragma unroll
    for (int mi = 0; mi < 2; mi++)
#pragma unroll
        for (int ni = 0; ni < 8; ni++)
#pragma unroll
            for (int q = 0; q < 4; q++) acc[mi][ni][q] = 0.f;

    cp16(dA0[0], asrc0, v0); cp16(dA1[0], asrc1, v1);
    cp16(dB0[0], bsrc0, true); cp16(dB1[0], bsrc1, true);
    CP_COMMIT();

    int buf = 0;
    for (int k0 = 0; k0 < INTER; k0 += BK) {
        if (k0 + BK < INTER) {
            int nb = buf ^ 1, kn = k0 + BK;
            cp16(dA0[nb], asrc0 + kn, v0); cp16(dA1[nb], asrc1 + kn, v1);
            cp16(dB0[nb], bsrc0 + kn, true); cp16(dB1[nb], bsrc1 + kn, true);
            CP_COMMIT();
            CP_WAIT1();
        } else {
            CP_WAIT0();
        }
        __syncthreads();
#pragma unroll
        for (int ks = 0; ks < 2; ks++) {
            int kb = ks * 8;
            uint32_t afr[2][4];
#pragma unroll
            for (int mi = 0; mi < 2; mi++) {
                const float* ab = &As[buf][(mw + mi * 16 + g) * SA + kb + tg];
                afr[mi][0] = __float_as_uint(ab[0]);
                afr[mi][1] = __float_as_uint(ab[8 * SA]);
                afr[mi][2] = __float_as_uint(ab[4]);
                afr[mi][3] = __float_as_uint(ab[8 * SA + 4]);
            }
#pragma unroll
            for (int ni = 0; ni < 8; ni++) {
                const float* bb = &Bs[buf][(nw + ni * 8 + g) * SA + kb + tg];
                uint32_t bf[2] = { __float_as_uint(bb[0]), __float_as_uint(bb[4]) };
#pragma unroll
                for (int mi = 0; mi < 2; mi++)
                    mma_tf32(acc[mi][ni], afr[mi], bf);
            }
        }
        __syncthreads();
        buf ^= 1;
    }

#pragma unroll
    for (int mi = 0; mi < 2; mi++)
#pragma unroll
        for (int h = 0; h < 2; h++) {
            int slot = m0 + mw + mi * 16 + g + h * 8;
            if (slot < cnt) {
                float wv = g_pair_w[e * T_TOK + slot];
                size_t base = ((size_t)e * T_TOK + slot) * DIM + n0 + nw;
#pragma unroll
                for (int ni = 0; ni < 8; ni++) {
                    float2 st;
                    st.x = acc[mi][ni][h * 2]     * wv;
                    st.y = acc[mi][ni][h * 2 + 1] * wv;
                    *(float2*)&g_pairout[base + ni * 8 + tg * 2] = st;
                }
            }
        }
}

// ---------------- kernel 4: combine (2 routed rows + shared row) ----------------
__global__ void combine_kernel(float* __restrict__ out) {
    int t = blockIdx.x;
    int r1 = g_tok_rows[2 * t], r2 = g_tok_rows[2 * t + 1];
    const float4* p1 = (const float4*)(g_pairout + (size_t)r1 * DIM);
    const float4* p2 = (const float4*)(g_pairout + (size_t)r2 * DIM);
    const float4* ps = (const float4*)(g_pairout + ((size_t)NEXP * T_TOK + t) * DIM);
    float4* o = (float4*)(out + (size_t)t * DIM);
#pragma unroll
    for (int i = threadIdx.x; i < DIM / 4; i += 256) {
        float4 a = p1[i], b = p2[i], c = ps[i];
        o[i] = make_float4(a.x + b.x + c.x, a.y + b.y + c.y,
                           a.z + b.z + c.z, a.w + b.w + c.w);
    }
}

// ---------------- launch ----------------
extern "C" void kernel_launch(void* const* d_in, const int* in_sizes, int n_in,
                              void* d_out, int out_size) {
    const float* x      = (const float*)d_in[0];
    const float* gate_w = (const float*)d_in[1];
    const float* w1     = (const float*)d_in[2];
    const float* w2     = (const float*)d_in[3];
    const float* w3     = (const float*)d_in[4];
    const float* ws1    = (const float*)d_in[5];
    const float* ws2    = (const float*)d_in[6];
    const float* ws3    = (const float*)d_in[7];
    float* out = (float*)d_out;

    init_kernel<<<1, 32>>>();

    // pre-round all weights to tf32 (device-global copies)
    float* w1c; cudaGetSymbolAddress((void**)&w1c, g_w1c);
    float* w3c; cudaGetSymbolAddress((void**)&w3c, g_w3c);
    float* w2c; cudaGetSymbolAddress((void**)&w2c, g_w2c);
    float* ws1c; cudaGetSymbolAddress((void**)&ws1c, g_ws1c);
    float* ws3c; cudaGetSymbolAddress((void**)&ws3c, g_ws3c);
    float* ws2c; cudaGetSymbolAddress((void**)&ws2c, g_ws2c);

    const int CB = 1024, CT = 256;
    convert_kernel<<<CB, CT>>>((const float4*)w1,  (float4*)w1c,  NEXP * INTER * DIM / 4);
    convert_kernel<<<CB, CT>>>((const float4*)w3,  (float4*)w3c,  NEXP * INTER * DIM / 4);
    convert_kernel<<<CB, CT>>>((const float4*)w2,  (float4*)w2c,  NEXP * DIM * INTER / 4);
    convert_kernel<<<CB, CT>>>((const float4*)ws1, (float4*)ws1c, INTER * DIM / 4);
    convert_kernel<<<CB, CT>>>((const float4*)ws3, (float4*)ws3c, INTER * DIM / 4);
    convert_kernel<<<CB, CT>>>((const float4*)ws2, (float4*)ws2c, DIM * INTER / 4);

    gate_kernel<<<T_TOK, 256>>>(x, gate_w);
    {
        dim3 grid(INTER / UP_BN, T_TOK / UP_BM, NE);
        up_kernel<<<grid, 256>>>();
    }
    {
        dim3 grid(DIM / DN_BN, T_TOK / DN_BM, NE);
        down_kernel<<<grid, 256>>>();
    }
    combine_kernel<<<T_TOK, 256>>>(out);
}

// round 8
// speedup vs baseline: 1.4061x; 1.4061x over previous
#include <cuda_runtime.h>
#include <cuda_fp16.h>
#include <stdint.h>
#include <math.h>

#define T_TOK 4096
#define DIM   2048
#define INTER 1024
#define NEXP  8
#define NE    9      // 8 routed + 1 shared pseudo-expert

// ---------------- scratch (device globals; no allocation allowed) ----------------
__device__ __half g_hidden [(size_t)NE * T_TOK * INTER];  // post-SwiGLU hidden (fp16)
__device__ float  g_pairout[(size_t)NE * T_TOK * DIM];    // weighted expert outputs
__device__ __half g_xh     [(size_t)T_TOK * DIM];         // fp16 activations
__device__ __half g_w1h [(size_t)NEXP * INTER * DIM];
__device__ __half g_w3h [(size_t)NEXP * INTER * DIM];
__device__ __half g_w2h [(size_t)NEXP * DIM * INTER];
__device__ __half g_ws1h[(size_t)INTER * DIM];
__device__ __half g_ws3h[(size_t)INTER * DIM];
__device__ __half g_ws2h[(size_t)DIM * INTER];
__device__ int    g_pair_tok[NE * T_TOK];
__device__ float  g_pair_w [NE * T_TOK];
__device__ int    g_tok_rows[T_TOK * 2];
__device__ int    g_cnt[NE];

// ---------------- PTX helpers ----------------
__device__ __forceinline__ uint32_t smem_u32(const void* p) {
    return (uint32_t)__cvta_generic_to_shared(p);
}
__device__ __forceinline__ void cp16(uint32_t dst, const void* src, bool valid) {
    int sz = valid ? 16 : 0;
    asm volatile("cp.async.cg.shared.global [%0], [%1], 16, %2;\n"
                 :: "r"(dst), "l"(src), "r"(sz));
}
#define CP_COMMIT() asm volatile("cp.async.commit_group;\n")
#define CP_WAIT1()  asm volatile("cp.async.wait_group 1;\n")
#define CP_WAIT0()  asm volatile("cp.async.wait_group 0;\n")

#define LDSM4(r0, r1, r2, r3, a) \
    asm volatile("ldmatrix.sync.aligned.m8n8.x4.shared.b16 {%0,%1,%2,%3}, [%4];" \
                 : "=r"(r0), "=r"(r1), "=r"(r2), "=r"(r3) : "r"(a))

#define MMA16816(c, a, b) \
    asm volatile("mma.sync.aligned.m16n8k16.row.col.f32.f16.f16.f32 " \
                 "{%0,%1,%2,%3},{%4,%5,%6,%7},{%8,%9},{%0,%1,%2,%3};" \
                 : "+f"((c)[0]), "+f"((c)[1]), "+f"((c)[2]), "+f"((c)[3]) \
                 : "r"((a)[0]), "r"((a)[1]), "r"((a)[2]), "r"((a)[3]), \
                   "r"((b)[0]), "r"((b)[1]))

// 64B-row swizzle: chunk (16B) index XORed with (row>>1)&3 -> conflict-free ldmatrix
__device__ __forceinline__ uint32_t swz(uint32_t row, uint32_t c) {
    return row * 64 + ((c ^ ((row >> 1) & 3)) << 4);
}

// ---------------- kernel 0: reset counters ----------------
__global__ void init_kernel() {
    int i = threadIdx.x;
    if (i < NE) g_cnt[i] = (i == NEXP) ? T_TOK : 0;
}

// ---------------- weight convert: f32 -> f16 ----------------
__global__ void convert_kernel(const float4* __restrict__ src,
                               uint2* __restrict__ dst, int n4) {
    int stride = gridDim.x * blockDim.x;
    for (int i = blockIdx.x * blockDim.x + threadIdx.x; i < n4; i += stride) {
        float4 v = src[i];
        __half2 a = __floats2half2_rn(v.x, v.y);
        __half2 b = __floats2half2_rn(v.z, v.w);
        uint2 o;
        o.x = *(uint32_t*)&a;
        o.y = *(uint32_t*)&b;
        dst[i] = o;
    }
}

// ---------------- gate: softmax + top2 + list build + fp16 x copy ----------------
__global__ void gate_kernel(const float* __restrict__ x,
                            const float* __restrict__ gw) {
    int t = blockIdx.x;
    const float* xr = x + (size_t)t * DIM;
    __half* xo = g_xh + (size_t)t * DIM;

    float acc[NEXP];
#pragma unroll
    for (int e = 0; e < NEXP; e++) acc[e] = 0.f;
    for (int d = threadIdx.x; d < DIM; d += 256) {
        float xv = xr[d];
        xo[d] = __float2half_rn(xv);
#pragma unroll
        for (int e = 0; e < NEXP; e++) acc[e] += xv * gw[e * DIM + d];
    }
#pragma unroll
    for (int off = 16; off > 0; off >>= 1) {
#pragma unroll
        for (int e = 0; e < NEXP; e++)
            acc[e] += __shfl_down_sync(0xffffffffu, acc[e], off);
    }
    __shared__ float sw[8][NEXP];
    int warp = threadIdx.x >> 5, lane = threadIdx.x & 31;
    if (lane == 0) {
#pragma unroll
        for (int e = 0; e < NEXP; e++) sw[warp][e] = acc[e];
    }
    __syncthreads();
    if (threadIdx.x == 0) {
        float lg[NEXP];
#pragma unroll
        for (int e = 0; e < NEXP; e++) {
            float s = 0.f;
#pragma unroll
            for (int w = 0; w < 8; w++) s += sw[w][e];
            lg[e] = s;
        }
        float mx = lg[0];
#pragma unroll
        for (int e = 1; e < NEXP; e++) mx = fmaxf(mx, lg[e]);
        float p[NEXP]; float sum = 0.f;
#pragma unroll
        for (int e = 0; e < NEXP; e++) { p[e] = expf(lg[e] - mx); sum += p[e]; }
        float inv = 1.f / sum;
#pragma unroll
        for (int e = 0; e < NEXP; e++) p[e] *= inv;
        int i1 = 0;
#pragma unroll
        for (int e = 1; e < NEXP; e++) if (p[e] > p[i1]) i1 = e;
        int i2 = (i1 == 0) ? 1 : 0;
#pragma unroll
        for (int e = 0; e < NEXP; e++) if (e != i1 && p[e] > p[i2]) i2 = e;

        int s1 = atomicAdd(&g_cnt[i1], 1);
        g_pair_tok[i1 * T_TOK + s1] = t;
        g_pair_w [i1 * T_TOK + s1] = p[i1];
        int s2 = atomicAdd(&g_cnt[i2], 1);
        g_pair_tok[i2 * T_TOK + s2] = t;
        g_pair_w [i2 * T_TOK + s2] = p[i2];
        g_tok_rows[2 * t]     = i1 * T_TOK + s1;
        g_tok_rows[2 * t + 1] = i2 * T_TOK + s2;
        g_pair_tok[NEXP * T_TOK + t] = t;
        g_pair_w [NEXP * T_TOK + t] = 1.0f;
    }
}

// ================= fp16 up-proj: H = silu(X W1^T) * (X W3^T) =================
// CTA tile M=128, N=64 (dual output), BK=32 halfs (64B rows). 3-stage ring, 16KB/stage.
// Stage layout: A[128x64B] @0, B1[64x64B] @8192, B3[64x64B] @12288.
__global__ __launch_bounds__(256, 2)
void up_kernel() {
    __shared__ __align__(1024) char tiles[3][16384];

    int e = blockIdx.z;
    int cnt = g_cnt[e];
    int m0 = blockIdx.y * 128;
    if (m0 >= cnt) return;
    int n0 = blockIdx.x * 64;

    const __half* B1 = (e < NEXP) ? g_w1h + (size_t)e * INTER * DIM : g_ws1h;
    const __half* B3 = (e < NEXP) ? g_w3h + (size_t)e * INTER * DIM : g_ws3h;

    int tid = threadIdx.x;
    int wid = tid >> 5, lane = tid & 31;
    uint32_t tb = smem_u32(tiles);

    // A loads: 512 chunks (128 rows x 4), 2 per thread. B1/B3: 256 chunks, 1 per thread.
    uint32_t aoff[2]; const __half* asrc[2]; bool aval[2];
#pragma unroll
    for (int j = 0; j < 2; j++) {
        int idx = tid + j * 256;
        int row = idx >> 2, c = idx & 3;
        aoff[j] = swz(row, c);
        int r = m0 + row;
        aval[j] = (r < cnt);
        int tok = aval[j] ? g_pair_tok[e * T_TOK + r] : 0;
        asrc[j] = g_xh + (size_t)tok * DIM + c * 8;
    }
    int brow = tid >> 2, bc = tid & 3;
    uint32_t boff = swz(brow, bc);
    const __half* b1src = B1 + (size_t)(n0 + brow) * DIM + bc * 8;
    const __half* b3src = B3 + (size_t)(n0 + brow) * DIM + bc * 8;

    int wm = (wid & 1) * 64, wn = (wid >> 1) * 16;
    int lr = lane & 15, lc = lane >> 4;
    int g = lane >> 2, tg = lane & 3;

    float acc1[4][2][4], acc3[4][2][4];
#pragma unroll
    for (int mi = 0; mi < 4; mi++)
#pragma unroll
        for (int ni = 0; ni < 2; ni++)
#pragma unroll
            for (int q = 0; q < 4; q++) { acc1[mi][ni][q] = 0.f; acc3[mi][ni][q] = 0.f; }

    const int NIT = DIM / 32;   // 64
#pragma unroll
    for (int st = 0; st < 2; st++) {
        uint32_t sb = tb + st * 16384;
#pragma unroll
        for (int j = 0; j < 2; j++) cp16(sb + aoff[j], asrc[j] + st * 32, aval[j]);
        cp16(sb + 8192  + boff, b1src + st * 32, true);
        cp16(sb + 12288 + boff, b3src + st * 32, true);
        CP_COMMIT();
    }

    for (int it = 0; it < NIT; it++) {
        if (it < NIT - 1) CP_WAIT1(); else CP_WAIT0();
        __syncthreads();
        int pf = it + 2;
        if (pf < NIT) {
            uint32_t sb = tb + (pf % 3) * 16384;
#pragma unroll
            for (int j = 0; j < 2; j++) cp16(sb + aoff[j], asrc[j] + pf * 32, aval[j]);
            cp16(sb + 8192  + boff, b1src + pf * 32, true);
            cp16(sb + 12288 + boff, b3src + pf * 32, true);
            CP_COMMIT();
        }
        uint32_t sb = tb + (it % 3) * 16384;
#pragma unroll
        for (int ks = 0; ks < 2; ks++) {
            uint32_t af[4][4];
#pragma unroll
            for (int mi = 0; mi < 4; mi++) {
                uint32_t a = sb + swz(wm + mi * 16 + lr, ks * 2 + lc);
                LDSM4(af[mi][0], af[mi][1], af[mi][2], af[mi][3], a);
            }
            uint32_t b1f[2][2], b3f[2][2];
            {
                uint32_t r0, r1, r2, r3;
                uint32_t a = sb + 8192 + swz(wn + lr, ks * 2 + lc);
                LDSM4(r0, r1, r2, r3, a);
                b1f[0][0] = r0; b1f[0][1] = r2; b1f[1][0] = r1; b1f[1][1] = r3;
                a = sb + 12288 + swz(wn + lr, ks * 2 + lc);
                LDSM4(r0, r1, r2, r3, a);
                b3f[0][0] = r0; b3f[0][1] = r2; b3f[1][0] = r1; b3f[1][1] = r3;
            }
#pragma unroll
            for (int mi = 0; mi < 4; mi++)
#pragma unroll
                for (int ni = 0; ni < 2; ni++) {
                    MMA16816(acc1[mi][ni], af[mi], b1f[ni]);
                    MMA16816(acc3[mi][ni], af[mi], b3f[ni]);
                }
        }
        __syncthreads();
    }

    // epilogue: silu(h1)*h3 -> g_hidden (fp16)
#pragma unroll
    for (int mi = 0; mi < 4; mi++)
#pragma unroll
        for (int h = 0; h < 2; h++) {
            int m = wm + mi * 16 + g + h * 8;
            int slot = m0 + m;
            if (slot < cnt) {
                __half* dst = g_hidden + ((size_t)e * T_TOK + slot) * INTER + n0;
#pragma unroll
                for (int ni = 0; ni < 2; ni++) {
                    int n = wn + ni * 8 + 2 * tg;
                    float h1a = acc1[mi][ni][h * 2], h1b = acc1[mi][ni][h * 2 + 1];
                    float h3a = acc3[mi][ni][h * 2], h3b = acc3[mi][ni][h * 2 + 1];
                    float va = (h1a / (1.f + __expf(-h1a))) * h3a;
                    float vb = (h1b / (1.f + __expf(-h1b))) * h3b;
                    *(__half2*)&dst[n] = __floats2half2_rn(va, vb);
                }
            }
        }
}

// ================= fp16 down-proj: O = H W2^T, weight-folded store =================
// CTA tile M=128, N=128, BK=32. Stage: A[128x64B] @0, B[128x64B] @8192.
__global__ __launch_bounds__(256, 2)
void down_kernel() {
    __shared__ __align__(1024) char tiles[3][16384];

    int e = blockIdx.z;
    int cnt = g_cnt[e];
    int m0 = blockIdx.y * 128;
    if (m0 >= cnt) return;
    int n0 = blockIdx.x * 128;

    const __half* B = (e < NEXP) ? g_w2h + (size_t)e * DIM * INTER : g_ws2h;

    int tid = threadIdx.x;
    int wid = tid >> 5, lane = tid & 31;
    uint32_t tb = smem_u32(tiles);

    uint32_t aoff[2]; const __half* asrc[2]; bool aval[2];
    uint32_t boff[2]; const __half* bsrc[2];
#pragma unroll
    for (int j = 0; j < 2; j++) {
        int idx = tid + j * 256;
        int row = idx >> 2, c = idx & 3;
        aoff[j] = swz(row, c);
        boff[j] = aoff[j];
        int r = m0 + row;
        aval[j] = (r < cnt);
        asrc[j] = g_hidden + ((size_t)e * T_TOK + (aval[j] ? r : 0)) * INTER + c * 8;
        bsrc[j] = B + (size_t)(n0 + row) * INTER + c * 8;
    }

    int wm = (wid & 1) * 64, wn = (wid >> 1) * 32;
    int lr = lane & 15, lc = lane >> 4;
    int g = lane >> 2, tg = lane & 3;

    float acc[4][4][4];
#pragma unroll
    for (int mi = 0; mi < 4; mi++)
#pragma unroll
        for (int ni = 0; ni < 4; ni++)
#pragma unroll
            for (int q = 0; q < 4; q++) acc[mi][ni][q] = 0.f;

    const int NIT = INTER / 32;   // 32
#pragma unroll
    for (int st = 0; st < 2; st++) {
        uint32_t sb = tb + st * 16384;
#pragma unroll
        for (int j = 0; j < 2; j++) cp16(sb + aoff[j], asrc[j] + st * 32, aval[j]);
#pragma unroll
        for (int j = 0; j < 2; j++) cp16(sb + 8192 + boff[j], bsrc[j] + st * 32, true);
        CP_COMMIT();
    }

    for (int it = 0; it < NIT; it++) {
        if (it < NIT - 1) CP_WAIT1(); else CP_WAIT0();
        __syncthreads();
        int pf = it + 2;
        if (pf < NIT) {
            uint32_t sb = tb + (pf % 3) * 16384;
#pragma unroll
            for (int j = 0; j < 2; j++) cp16(sb + aoff[j], asrc[j] + pf * 32, aval[j]);
#pragma unroll
            for (int j = 0; j < 2; j++) cp16(sb + 8192 + boff[j], bsrc[j] + pf * 32, true);
            CP_COMMIT();
        }
        uint32_t sb = tb + (it % 3) * 16384;
#pragma unroll
        for (int ks = 0; ks < 2; ks++) {
            uint32_t af[4][4];
#pragma unroll
            for (int mi = 0; mi < 4; mi++) {
                uint32_t a = sb + swz(wm + mi * 16 + lr, ks * 2 + lc);
                LDSM4(af[mi][0], af[mi][1], af[mi][2], af[mi][3], a);
            }
            uint32_t bf[4][2];
#pragma unroll
            for (int bi = 0; bi < 2; bi++) {
                uint32_t r0, r1, r2, r3;
                uint32_t a = sb + 8192 + swz(wn + bi * 16 + lr, ks * 2 + lc);
                LDSM4(r0, r1, r2, r3, a);
                bf[bi * 2][0] = r0; bf[bi * 2][1] = r2;
                bf[bi * 2 + 1][0] = r1; bf[bi * 2 + 1][1] = r3;
            }
#pragma unroll
            for (int mi = 0; mi < 4; mi++)
#pragma unroll
                for (int ni = 0; ni < 4; ni++)
                    MMA16816(acc[mi][ni], af[mi], bf[ni]);
        }
        __syncthreads();
    }

    // epilogue: weight-fold + store to pairout
#pragma unroll
    for (int mi = 0; mi < 4; mi++)
#pragma unroll
        for (int h = 0; h < 2; h++) {
            int m = wm + mi * 16 + g + h * 8;
            int slot = m0 + m;
            if (slot < cnt) {
                float wv = g_pair_w[e * T_TOK + slot];
                float* dst = g_pairout + ((size_t)e * T_TOK + slot) * DIM + n0;
#pragma unroll
                for (int ni = 0; ni < 4; ni++) {
                    int n = wn + ni * 8 + 2 * tg;
                    float2 st;
                    st.x = acc[mi][ni][h * 2]     * wv;
                    st.y = acc[mi][ni][h * 2 + 1] * wv;
                    *(float2*)&dst[n] = st;
                }
            }
        }
}

// ---------------- combine (2 routed rows + shared row) ----------------
__global__ void combine_kernel(float* __restrict__ out) {
    int t = blockIdx.x;
    int r1 = g_tok_rows[2 * t], r2 = g_tok_rows[2 * t + 1];
    const float4* p1 = (const float4*)(g_pairout + (size_t)r1 * DIM);
    const float4* p2 = (const float4*)(g_pairout + (size_t)r2 * DIM);
    const float4* ps = (const float4*)(g_pairout + ((size_t)NEXP * T_TOK + t) * DIM);
    float4* o = (float4*)(out + (size_t)t * DIM);
#pragma unroll
    for (int i = threadIdx.x; i < DIM / 4; i += 256) {
        float4 a = p1[i], b = p2[i], c = ps[i];
        o[i] = make_float4(a.x + b.x + c.x, a.y + b.y + c.y,
                           a.z + b.z + c.z, a.w + b.w + c.w);
    }
}

// ---------------- launch ----------------
extern "C" void kernel_launch(void* const* d_in, const int* in_sizes, int n_in,
                              void* d_out, int out_size) {
    const float* x      = (const float*)d_in[0];
    const float* gate_w = (const float*)d_in[1];
    const float* w1     = (const float*)d_in[2];
    const float* w2     = (const float*)d_in[3];
    const float* w3     = (const float*)d_in[4];
    const float* ws1    = (const float*)d_in[5];
    const float* ws2    = (const float*)d_in[6];
    const float* ws3    = (const float*)d_in[7];
    float* out = (float*)d_out;

    init_kernel<<<1, 32>>>();

    __half* w1h;  cudaGetSymbolAddress((void**)&w1h,  g_w1h);
    __half* w3h;  cudaGetSymbolAddress((void**)&w3h,  g_w3h);
    __half* w2h;  cudaGetSymbolAddress((void**)&w2h,  g_w2h);
    __half* ws1h; cudaGetSymbolAddress((void**)&ws1h, g_ws1h);
    __half* ws3h; cudaGetSymbolAddress((void**)&ws3h, g_ws3h);
    __half* ws2h; cudaGetSymbolAddress((void**)&ws2h, g_ws2h);

    const int CB = 1024, CT = 256;
    convert_kernel<<<CB, CT>>>((const float4*)w1,  (uint2*)w1h,  NEXP * INTER * DIM / 4);
    convert_kernel<<<CB, CT>>>((const float4*)w3,  (uint2*)w3h,  NEXP * INTER * DIM / 4);
    convert_kernel<<<CB, CT>>>((const float4*)w2,  (uint2*)w2h,  NEXP * DIM * INTER / 4);
    convert_kernel<<<CB, CT>>>((const float4*)ws1, (uint2*)ws1h, INTER * DIM / 4);
    convert_kernel<<<CB, CT>>>((const float4*)ws3, (uint2*)ws3h, INTER * DIM / 4);
    convert_kernel<<<CB, CT>>>((const float4*)ws2, (uint2*)ws2h, DIM * INTER / 4);

    gate_kernel<<<T_TOK, 256>>>(x, gate_w);
    {
        dim3 grid(INTER / 64, T_TOK / 128, NE);
        up_kernel<<<grid, 256>>>();
    }
    {
        dim3 grid(DIM / 128, T_TOK / 128, NE);
        down_kernel<<<grid, 256>>>();
    }
    combine_kernel<<<T_TOK, 256>>>(out);
}

// round 9
// speedup vs baseline: 2.1063x; 1.4980x over previous
#include <cuda_runtime.h>
#include <cuda_fp16.h>
#include <stdint.h>
#include <math.h>

#define T_TOK 4096
#define DIM   2048
#define INTER 1024
#define NEXP  8
#define NE    9      // 8 routed + 1 shared pseudo-expert

// ---------------- scratch (device globals; no allocation allowed) ----------------
__device__ __half g_hidden [(size_t)NE * T_TOK * INTER];  // post-SwiGLU hidden (fp16)
__device__ float  g_pairout[(size_t)NE * T_TOK * DIM];    // weighted expert outputs
__device__ __half g_xh     [(size_t)T_TOK * DIM];         // fp16 activations
__device__ __half g_w1h [(size_t)NEXP * INTER * DIM];
__device__ __half g_w3h [(size_t)NEXP * INTER * DIM];
__device__ __half g_w2h [(size_t)NEXP * DIM * INTER];
__device__ __half g_ws1h[(size_t)INTER * DIM];
__device__ __half g_ws3h[(size_t)INTER * DIM];
__device__ __half g_ws2h[(size_t)DIM * INTER];
__device__ int    g_pair_tok[NE * T_TOK];
__device__ float  g_pair_w [NE * T_TOK];
__device__ int    g_tok_rows[T_TOK * 2];
__device__ int    g_cnt[NE];

// ---------------- PTX helpers ----------------
__device__ __forceinline__ uint32_t smem_u32(const void* p) {
    return (uint32_t)__cvta_generic_to_shared(p);
}
__device__ __forceinline__ void cp16(uint32_t dst, const void* src, bool valid) {
    int sz = valid ? 16 : 0;
    asm volatile("cp.async.cg.shared.global [%0], [%1], 16, %2;\n"
                 :: "r"(dst), "l"(src), "r"(sz));
}
#define CP_COMMIT() asm volatile("cp.async.commit_group;\n")
#define CP_WAIT1()  asm volatile("cp.async.wait_group 1;\n")
#define CP_WAIT0()  asm volatile("cp.async.wait_group 0;\n")

#define LDSM4(r0, r1, r2, r3, a) \
    asm volatile("ldmatrix.sync.aligned.m8n8.x4.shared.b16 {%0,%1,%2,%3}, [%4];" \
                 : "=r"(r0), "=r"(r1), "=r"(r2), "=r"(r3) : "r"(a))

#define MMA16816(c, a, b) \
    asm volatile("mma.sync.aligned.m16n8k16.row.col.f32.f16.f16.f32 " \
                 "{%0,%1,%2,%3},{%4,%5,%6,%7},{%8,%9},{%0,%1,%2,%3};" \
                 : "+f"((c)[0]), "+f"((c)[1]), "+f"((c)[2]), "+f"((c)[3]) \
                 : "r"((a)[0]), "r"((a)[1]), "r"((a)[2]), "r"((a)[3]), \
                   "r"((b)[0]), "r"((b)[1]))

// 64B-row swizzle: chunk (16B) index XORed with (row>>1)&3 -> conflict-free ldmatrix
__device__ __forceinline__ uint32_t swz(uint32_t row, uint32_t c) {
    return row * 64 + ((c ^ ((row >> 1) & 3)) << 4);
}

// ---------------- merged convert (+init): f32 -> f16 over 6 segments ----------------
struct Seg { const float4* src; uint2* dst; int n4; };

__global__ void convert_all_kernel(Seg s0, Seg s1, Seg s2, Seg s3, Seg s4, Seg s5) {
    if (blockIdx.x == 0 && threadIdx.x < NE)
        g_cnt[threadIdx.x] = (threadIdx.x == NEXP) ? T_TOK : 0;
    Seg segs[6] = { s0, s1, s2, s3, s4, s5 };
    int stride = gridDim.x * blockDim.x;
    int tid = blockIdx.x * blockDim.x + threadIdx.x;
#pragma unroll
    for (int s = 0; s < 6; s++) {
        const float4* src = segs[s].src;
        uint2* dst = segs[s].dst;
        int n4 = segs[s].n4;
        for (int i = tid; i < n4; i += stride) {
            float4 v = src[i];
            __half2 a = __floats2half2_rn(v.x, v.y);
            __half2 b = __floats2half2_rn(v.z, v.w);
            uint2 o;
            o.x = *(uint32_t*)&a;
            o.y = *(uint32_t*)&b;
            dst[i] = o;
        }
    }
}

// ---------------- gate: softmax + top2 + list build + fp16 x copy ----------------
__global__ void gate_kernel(const float* __restrict__ x,
                            const float* __restrict__ gw) {
    int t = blockIdx.x;
    const float* xr = x + (size_t)t * DIM;
    __half* xo = g_xh + (size_t)t * DIM;

    float acc[NEXP];
#pragma unroll
    for (int e = 0; e < NEXP; e++) acc[e] = 0.f;
    for (int d = threadIdx.x; d < DIM; d += 256) {
        float xv = xr[d];
        xo[d] = __float2half_rn(xv);
#pragma unroll
        for (int e = 0; e < NEXP; e++) acc[e] += xv * gw[e * DIM + d];
    }
#pragma unroll
    for (int off = 16; off > 0; off >>= 1) {
#pragma unroll
        for (int e = 0; e < NEXP; e++)
            acc[e] += __shfl_down_sync(0xffffffffu, acc[e], off);
    }
    __shared__ float sw[8][NEXP];
    int warp = threadIdx.x >> 5, lane = threadIdx.x & 31;
    if (lane == 0) {
#pragma unroll
        for (int e = 0; e < NEXP; e++) sw[warp][e] = acc[e];
    }
    __syncthreads();
    if (threadIdx.x == 0) {
        float lg[NEXP];
#pragma unroll
        for (int e = 0; e < NEXP; e++) {
            float s = 0.f;
#pragma unroll
            for (int w = 0; w < 8; w++) s += sw[w][e];
            lg[e] = s;
        }
        float mx = lg[0];
#pragma unroll
        for (int e = 1; e < NEXP; e++) mx = fmaxf(mx, lg[e]);
        float p[NEXP]; float sum = 0.f;
#pragma unroll
        for (int e = 0; e < NEXP; e++) { p[e] = expf(lg[e] - mx); sum += p[e]; }
        float inv = 1.f / sum;
#pragma unroll
        for (int e = 0; e < NEXP; e++) p[e] *= inv;
        int i1 = 0;
#pragma unroll
        for (int e = 1; e < NEXP; e++) if (p[e] > p[i1]) i1 = e;
        int i2 = (i1 == 0) ? 1 : 0;
#pragma unroll
        for (int e = 0; e < NEXP; e++) if (e != i1 && p[e] > p[i2]) i2 = e;

        int s1 = atomicAdd(&g_cnt[i1], 1);
        g_pair_tok[i1 * T_TOK + s1] = t;
        g_pair_w [i1 * T_TOK + s1] = p[i1];
        int s2 = atomicAdd(&g_cnt[i2], 1);
        g_pair_tok[i2 * T_TOK + s2] = t;
        g_pair_w [i2 * T_TOK + s2] = p[i2];
        g_tok_rows[2 * t]     = i1 * T_TOK + s1;
        g_tok_rows[2 * t + 1] = i2 * T_TOK + s2;
        g_pair_tok[NEXP * T_TOK + t] = t;
        g_pair_w [NEXP * T_TOK + t] = 1.0f;
    }
}

// ================= fp16 up-proj: H = silu(X W1^T) * (X W3^T) =================
// CTA tile M=128, N=64 (dual output), BK=32 halfs. 3-stage ring, ONE sync/iter.
__global__ __launch_bounds__(256, 2)
void up_kernel() {
    __shared__ __align__(1024) char tiles[3][16384];

    int e = blockIdx.z;
    int cnt = g_cnt[e];
    int m0 = blockIdx.y * 128;
    if (m0 >= cnt) return;
    int n0 = blockIdx.x * 64;

    const __half* B1 = (e < NEXP) ? g_w1h + (size_t)e * INTER * DIM : g_ws1h;
    const __half* B3 = (e < NEXP) ? g_w3h + (size_t)e * INTER * DIM : g_ws3h;

    int tid = threadIdx.x;
    int wid = tid >> 5, lane = tid & 31;
    uint32_t tb = smem_u32(tiles);

    uint32_t aoff[2]; const __half* asrc[2]; bool aval[2];
#pragma unroll
    for (int j = 0; j < 2; j++) {
        int idx = tid + j * 256;
        int row = idx >> 2, c = idx & 3;
        aoff[j] = swz(row, c);
        int r = m0 + row;
        aval[j] = (r < cnt);
        int tok = aval[j] ? g_pair_tok[e * T_TOK + r] : 0;
        asrc[j] = g_xh + (size_t)tok * DIM + c * 8;
    }
    int brow = tid >> 2, bc = tid & 3;
    uint32_t boff = swz(brow, bc);
    const __half* b1src = B1 + (size_t)(n0 + brow) * DIM + bc * 8;
    const __half* b3src = B3 + (size_t)(n0 + brow) * DIM + bc * 8;

    int wm = (wid & 1) * 64, wn = (wid >> 1) * 16;
    int lr = lane & 15, lc = lane >> 4;
    int g = lane >> 2, tg = lane & 3;

    float acc1[4][2][4], acc3[4][2][4];
#pragma unroll
    for (int mi = 0; mi < 4; mi++)
#pragma unroll
        for (int ni = 0; ni < 2; ni++)
#pragma unroll
            for (int q = 0; q < 4; q++) { acc1[mi][ni][q] = 0.f; acc3[mi][ni][q] = 0.f; }

    const int NIT = DIM / 32;   // 64
#pragma unroll
    for (int st = 0; st < 2; st++) {
        uint32_t sb = tb + st * 16384;
#pragma unroll
        for (int j = 0; j < 2; j++) cp16(sb + aoff[j], asrc[j] + st * 32, aval[j]);
        cp16(sb + 8192  + boff, b1src + st * 32, true);
        cp16(sb + 12288 + boff, b3src + st * 32, true);
        CP_COMMIT();
    }

    for (int it = 0; it < NIT; it++) {
        if (it < NIT - 1) CP_WAIT1(); else CP_WAIT0();
        __syncthreads();      // single barrier: guards stage it ready AND stage it+2 free
        int pf = it + 2;
        if (pf < NIT) {
            uint32_t sb = tb + (pf % 3) * 16384;
#pragma unroll
            for (int j = 0; j < 2; j++) cp16(sb + aoff[j], asrc[j] + pf * 32, aval[j]);
            cp16(sb + 8192  + boff, b1src + pf * 32, true);
            cp16(sb + 12288 + boff, b3src + pf * 32, true);
            CP_COMMIT();
        }
        uint32_t sb = tb + (it % 3) * 16384;
#pragma unroll
        for (int ks = 0; ks < 2; ks++) {
            uint32_t af[4][4];
#pragma unroll
            for (int mi = 0; mi < 4; mi++) {
                uint32_t a = sb + swz(wm + mi * 16 + lr, ks * 2 + lc);
                LDSM4(af[mi][0], af[mi][1], af[mi][2], af[mi][3], a);
            }
            uint32_t b1f[2][2], b3f[2][2];
            {
                uint32_t r0, r1, r2, r3;
                uint32_t a = sb + 8192 + swz(wn + lr, ks * 2 + lc);
                LDSM4(r0, r1, r2, r3, a);
                b1f[0][0] = r0; b1f[0][1] = r2; b1f[1][0] = r1; b1f[1][1] = r3;
                a = sb + 12288 + swz(wn + lr, ks * 2 + lc);
                LDSM4(r0, r1, r2, r3, a);
                b3f[0][0] = r0; b3f[0][1] = r2; b3f[1][0] = r1; b3f[1][1] = r3;
            }
#pragma unroll
            for (int mi = 0; mi < 4; mi++)
#pragma unroll
                for (int ni = 0; ni < 2; ni++) {
                    MMA16816(acc1[mi][ni], af[mi], b1f[ni]);
                    MMA16816(acc3[mi][ni], af[mi], b3f[ni]);
                }
        }
    }

    // epilogue: silu(h1)*h3 -> g_hidden (fp16)
#pragma unroll
    for (int mi = 0; mi < 4; mi++)
#pragma unroll
        for (int h = 0; h < 2; h++) {
            int m = wm + mi * 16 + g + h * 8;
            int slot = m0 + m;
            if (slot < cnt) {
                __half* dst = g_hidden + ((size_t)e * T_TOK + slot) * INTER + n0;
#pragma unroll
                for (int ni = 0; ni < 2; ni++) {
                    int n = wn + ni * 8 + 2 * tg;
                    float h1a = acc1[mi][ni][h * 2], h1b = acc1[mi][ni][h * 2 + 1];
                    float h3a = acc3[mi][ni][h * 2], h3b = acc3[mi][ni][h * 2 + 1];
                    float va = (h1a / (1.f + __expf(-h1a))) * h3a;
                    float vb = (h1b / (1.f + __expf(-h1b))) * h3b;
                    *(__half2*)&dst[n] = __floats2half2_rn(va, vb);
                }
            }
        }
}

// ================= fp16 down-proj: O = H W2^T, weight-folded store =================
__global__ __launch_bounds__(256, 2)
void down_kernel() {
    __shared__ __align__(1024) char tiles[3][16384];

    int e = blockIdx.z;
    int cnt = g_cnt[e];
    int m0 = blockIdx.y * 128;
    if (m0 >= cnt) return;
    int n0 = blockIdx.x * 128;

    const __half* B = (e < NEXP) ? g_w2h + (size_t)e * DIM * INTER : g_ws2h;

    int tid = threadIdx.x;
    int wid = tid >> 5, lane = tid & 31;
    uint32_t tb = smem_u32(tiles);

    uint32_t aoff[2]; const __half* asrc[2]; bool aval[2];
    const __half* bsrc[2];
#pragma unroll
    for (int j = 0; j < 2; j++) {
        int idx = tid + j * 256;
        int row = idx >> 2, c = idx & 3;
        aoff[j] = swz(row, c);
        int r = m0 + row;
        aval[j] = (r < cnt);
        asrc[j] = g_hidden + ((size_t)e * T_TOK + (aval[j] ? r : 0)) * INTER + c * 8;
        bsrc[j] = B + (size_t)(n0 + row) * INTER + c * 8;
    }

    int wm = (wid & 1) * 64, wn = (wid >> 1) * 32;
    int lr = lane & 15, lc = lane >> 4;
    int g = lane >> 2, tg = lane & 3;

    float acc[4][4][4];
#pragma unroll
    for (int mi = 0; mi < 4; mi++)
#pragma unroll
        for (int ni = 0; ni < 4; ni++)
#pragma unroll
            for (int q = 0; q < 4; q++) acc[mi][ni][q] = 0.f;

    const int NIT = INTER / 32;   // 32
#pragma unroll
    for (int st = 0; st < 2; st++) {
        uint32_t sb = tb + st * 16384;
#pragma unroll
        for (int j = 0; j < 2; j++) cp16(sb + aoff[j], asrc[j] + st * 32, aval[j]);
#pragma unroll
        for (int j = 0; j < 2; j++) cp16(sb + 8192 + aoff[j], bsrc[j] + st * 32, true);
        CP_COMMIT();
    }

    for (int it = 0; it < NIT; it++) {
        if (it < NIT - 1) CP_WAIT1(); else CP_WAIT0();
        __syncthreads();      // single barrier per iter
        int pf = it + 2;
        if (pf < NIT) {
            uint32_t sb = tb + (pf % 3) * 16384;
#pragma unroll
            for (int j = 0; j < 2; j++) cp16(sb + aoff[j], asrc[j] + pf * 32, aval[j]);
#pragma unroll
            for (int j = 0; j < 2; j++) cp16(sb + 8192 + aoff[j], bsrc[j] + pf * 32, true);
            CP_COMMIT();
        }
        uint32_t sb = tb + (it % 3) * 16384;
#pragma unroll
        for (int ks = 0; ks < 2; ks++) {
            uint32_t af[4][4];
#pragma unroll
            for (int mi = 0; mi < 4; mi++) {
                uint32_t a = sb + swz(wm + mi * 16 + lr, ks * 2 + lc);
                LDSM4(af[mi][0], af[mi][1], af[mi][2], af[mi][3], a);
            }
            uint32_t bf[4][2];
#pragma unroll
            for (int bi = 0; bi < 2; bi++) {
                uint32_t r0, r1, r2, r3;
                uint32_t a = sb + 8192 + swz(wn + bi * 16 + lr, ks * 2 + lc);
                LDSM4(r0, r1, r2, r3, a);
                bf[bi * 2][0] = r0; bf[bi * 2][1] = r2;
                bf[bi * 2 + 1][0] = r1; bf[bi * 2 + 1][1] = r3;
            }
#pragma unroll
            for (int mi = 0; mi < 4; mi++)
#pragma unroll
                for (int ni = 0; ni < 4; ni++)
                    MMA16816(acc[mi][ni], af[mi], bf[ni]);
        }
    }

    // epilogue: weight-fold + store to pairout
#pragma unroll
    for (int mi = 0; mi < 4; mi++)
#pragma unroll
        for (int h = 0; h < 2; h++) {
            int m = wm + mi * 16 + g + h * 8;
            int slot = m0 + m;
            if (slot < cnt) {
                float wv = g_pair_w[e * T_TOK + slot];
                float* dst = g_pairout + ((size_t)e * T_TOK + slot) * DIM + n0;
#pragma unroll
                for (int ni = 0; ni < 4; ni++) {
                    int n = wn + ni * 8 + 2 * tg;
                    float2 st;
                    st.x = acc[mi][ni][h * 2]     * wv;
                    st.y = acc[mi][ni][h * 2 + 1] * wv;
                    *(float2*)&dst[n] = st;
                }
            }
        }
}

// ---------------- combine (2 routed rows + shared row) ----------------
__global__ void combine_kernel(float* __restrict__ out) {
    int t = blockIdx.x;
    int r1 = g_tok_rows[2 * t], r2 = g_tok_rows[2 * t + 1];
    const float4* p1 = (const float4*)(g_pairout + (size_t)r1 * DIM);
    const float4* p2 = (const float4*)(g_pairout + (size_t)r2 * DIM);
    const float4* ps = (const float4*)(g_pairout + ((size_t)NEXP * T_TOK + t) * DIM);
    float4* o = (float4*)(out + (size_t)t * DIM);
#pragma unroll
    for (int i = threadIdx.x; i < DIM / 4; i += 256) {
        float4 a = p1[i], b = p2[i], c = ps[i];
        o[i] = make_float4(a.x + b.x + c.x, a.y + b.y + c.y,
                           a.z + b.z + c.z, a.w + b.w + c.w);
    }
}

// ---------------- launch ----------------
extern "C" void kernel_launch(void* const* d_in, const int* in_sizes, int n_in,
                              void* d_out, int out_size) {
    const float* x      = (const float*)d_in[0];
    const float* gate_w = (const float*)d_in[1];
    const float* w1     = (const float*)d_in[2];
    const float* w2     = (const float*)d_in[3];
    const float* w3     = (const float*)d_in[4];
    const float* ws1    = (const float*)d_in[5];
    const float* ws2    = (const float*)d_in[6];
    const float* ws3    = (const float*)d_in[7];
    float* out = (float*)d_out;

    __half* w1h;  cudaGetSymbolAddress((void**)&w1h,  g_w1h);
    __half* w3h;  cudaGetSymbolAddress((void**)&w3h,  g_w3h);
    __half* w2h;  cudaGetSymbolAddress((void**)&w2h,  g_w2h);
    __half* ws1h; cudaGetSymbolAddress((void**)&ws1h, g_ws1h);
    __half* ws3h; cudaGetSymbolAddress((void**)&ws3h, g_ws3h);
    __half* ws2h; cudaGetSymbolAddress((void**)&ws2h, g_ws2h);

    Seg s0 = { (const float4*)w1,  (uint2*)w1h,  NEXP * INTER * DIM / 4 };
    Seg s1 = { (const float4*)w3,  (uint2*)w3h,  NEXP * INTER * DIM / 4 };
    Seg s2 = { (const float4*)w2,  (uint2*)w2h,  NEXP * DIM * INTER / 4 };
    Seg s3 = { (const float4*)ws1, (uint2*)ws1h, INTER * DIM / 4 };
    Seg s4 = { (const float4*)ws3, (uint2*)ws3h, INTER * DIM / 4 };
    Seg s5 = { (const float4*)ws2, (uint2*)ws2h, DIM * INTER / 4 };
    convert_all_kernel<<<2048, 256>>>(s0, s1, s2, s3, s4, s5);

    gate_kernel<<<T_TOK, 256>>>(x, gate_w);
    {
        dim3 grid(INTER / 64, T_TOK / 128, NE);
        up_kernel<<<grid, 256>>>();
    }
    {
        dim3 grid(DIM / 128, T_TOK / 128, NE);
        down_kernel<<<grid, 256>>>();
    }
    combine_kernel<<<T_TOK, 256>>>(out);
}

// round 10
// speedup vs baseline: 2.3214x; 1.1021x over previous
#include <cuda_runtime.h>
#include <cuda_fp16.h>
#include <stdint.h>
#include <math.h>

#define T_TOK 4096
#define DIM   2048
#define INTER 1024
#define NEXP  8
#define NE    9      // 8 routed + 1 shared pseudo-expert

// ---------------- scratch (device globals; no allocation allowed) ----------------
__device__ __half g_hidden [(size_t)NE * T_TOK * INTER];  // post-SwiGLU hidden (fp16)
__device__ float  g_pairout[(size_t)NE * T_TOK * DIM];    // weighted expert outputs
__device__ __half g_xh     [(size_t)T_TOK * DIM];         // fp16 activations
__device__ __half g_w1h [(size_t)NEXP * INTER * DIM];
__device__ __half g_w3h [(size_t)NEXP * INTER * DIM];
__device__ __half g_w2h [(size_t)NEXP * DIM * INTER];
__device__ __half g_ws1h[(size_t)INTER * DIM];
__device__ __half g_ws3h[(size_t)INTER * DIM];
__device__ __half g_ws2h[(size_t)DIM * INTER];
__device__ int    g_pair_tok[NE * T_TOK];
__device__ float  g_pair_w [NE * T_TOK];
__device__ int    g_tok_rows[T_TOK * 2];
__device__ int    g_cnt[NE];

// ---------------- PTX helpers ----------------
__device__ __forceinline__ uint32_t smem_u32(const void* p) {
    return (uint32_t)__cvta_generic_to_shared(p);
}
__device__ __forceinline__ void cp16(uint32_t dst, const void* src, bool valid) {
    int sz = valid ? 16 : 0;
    asm volatile("cp.async.cg.shared.global [%0], [%1], 16, %2;\n"
                 :: "r"(dst), "l"(src), "r"(sz));
}
#define CP_COMMIT() asm volatile("cp.async.commit_group;\n")
#define CP_WAIT1()  asm volatile("cp.async.wait_group 1;\n")
#define CP_WAIT0()  asm volatile("cp.async.wait_group 0;\n")

#define LDSM4(r0, r1, r2, r3, a) \
    asm volatile("ldmatrix.sync.aligned.m8n8.x4.shared.b16 {%0,%1,%2,%3}, [%4];" \
                 : "=r"(r0), "=r"(r1), "=r"(r2), "=r"(r3) : "r"(a))

#define MMA16816(c, a, b) \
    asm volatile("mma.sync.aligned.m16n8k16.row.col.f32.f16.f16.f32 " \
                 "{%0,%1,%2,%3},{%4,%5,%6,%7},{%8,%9},{%0,%1,%2,%3};" \
                 : "+f"((c)[0]), "+f"((c)[1]), "+f"((c)[2]), "+f"((c)[3]) \
                 : "r"((a)[0]), "r"((a)[1]), "r"((a)[2]), "r"((a)[3]), \
                   "r"((b)[0]), "r"((b)[1]))

// SW128 swizzle for 128B rows: 16B chunk index XOR row%8 -> conflict-free LDSM + cp.async
__device__ __forceinline__ uint32_t swz(uint32_t row, uint32_t c) {
    return row * 128 + ((c ^ (row & 7)) << 4);
}

// ---------------- merged convert (+init): f32 -> f16 over 6 segments ----------------
struct Seg { const float4* src; uint2* dst; int n4; };

__global__ void convert_all_kernel(Seg s0, Seg s1, Seg s2, Seg s3, Seg s4, Seg s5) {
    if (blockIdx.x == 0 && threadIdx.x < NE)
        g_cnt[threadIdx.x] = (threadIdx.x == NEXP) ? T_TOK : 0;
    Seg segs[6] = { s0, s1, s2, s3, s4, s5 };
    int stride = gridDim.x * blockDim.x;
    int tid = blockIdx.x * blockDim.x + threadIdx.x;
#pragma unroll
    for (int s = 0; s < 6; s++) {
        const float4* src = segs[s].src;
        uint2* dst = segs[s].dst;
        int n4 = segs[s].n4;
        for (int i = tid; i < n4; i += stride) {
            float4 v = src[i];
            __half2 a = __floats2half2_rn(v.x, v.y);
            __half2 b = __floats2half2_rn(v.z, v.w);
            uint2 o;
            o.x = *(uint32_t*)&a;
            o.y = *(uint32_t*)&b;
            dst[i] = o;
        }
    }
}

// ---------------- gate: softmax + top2 + list build + fp16 x copy ----------------
__global__ void gate_kernel(const float* __restrict__ x,
                            const float* __restrict__ gw) {
    int t = blockIdx.x;
    const float* xr = x + (size_t)t * DIM;
    __half* xo = g_xh + (size_t)t * DIM;

    float acc[NEXP];
#pragma unroll
    for (int e = 0; e < NEXP; e++) acc[e] = 0.f;
    for (int d = threadIdx.x; d < DIM; d += 256) {
        float xv = xr[d];
        xo[d] = __float2half_rn(xv);
#pragma unroll
        for (int e = 0; e < NEXP; e++) acc[e] += xv * gw[e * DIM + d];
    }
#pragma unroll
    for (int off = 16; off > 0; off >>= 1) {
#pragma unroll
        for (int e = 0; e < NEXP; e++)
            acc[e] += __shfl_down_sync(0xffffffffu, acc[e], off);
    }
    __shared__ float sw[8][NEXP];
    int warp = threadIdx.x >> 5, lane = threadIdx.x & 31;
    if (lane == 0) {
#pragma unroll
        for (int e = 0; e < NEXP; e++) sw[warp][e] = acc[e];
    }
    __syncthreads();
    if (threadIdx.x == 0) {
        float lg[NEXP];
#pragma unroll
        for (int e = 0; e < NEXP; e++) {
            float s = 0.f;
#pragma unroll
            for (int w = 0; w < 8; w++) s += sw[w][e];
            lg[e] = s;
        }
        float mx = lg[0];
#pragma unroll
        for (int e = 1; e < NEXP; e++) mx = fmaxf(mx, lg[e]);
        float p[NEXP]; float sum = 0.f;
#pragma unroll
        for (int e = 0; e < NEXP; e++) { p[e] = expf(lg[e] - mx); sum += p[e]; }
        float inv = 1.f / sum;
#pragma unroll
        for (int e = 0; e < NEXP; e++) p[e] *= inv;
        int i1 = 0;
#pragma unroll
        for (int e = 1; e < NEXP; e++) if (p[e] > p[i1]) i1 = e;
        int i2 = (i1 == 0) ? 1 : 0;
#pragma unroll
        for (int e = 0; e < NEXP; e++) if (e != i1 && p[e] > p[i2]) i2 = e;

        int s1 = atomicAdd(&g_cnt[i1], 1);
        g_pair_tok[i1 * T_TOK + s1] = t;
        g_pair_w [i1 * T_TOK + s1] = p[i1];
        int s2 = atomicAdd(&g_cnt[i2], 1);
        g_pair_tok[i2 * T_TOK + s2] = t;
        g_pair_w [i2 * T_TOK + s2] = p[i2];
        g_tok_rows[2 * t]     = i1 * T_TOK + s1;
        g_tok_rows[2 * t + 1] = i2 * T_TOK + s2;
        g_pair_tok[NEXP * T_TOK + t] = t;
        g_pair_w [NEXP * T_TOK + t] = 1.0f;
    }
}

// ================= fp16 up-proj: H = silu(X W1^T) * (X W3^T) =================
// CTA tile M=128, N=64 dual-matrix. BK=64 halfs (128B SW128 rows), 3-stage x 32KB.
// Stage: A[128x128B] @0, B1[64x128B] @16384, B3[64x128B] @24576.
#define UPSTG 32768

__global__ __launch_bounds__(256, 2)
void up_kernel() {
    extern __shared__ __align__(1024) char dsm[];

    int e = blockIdx.z;
    int cnt = g_cnt[e];
    int m0 = blockIdx.y * 128;
    if (m0 >= cnt) return;
    int n0 = blockIdx.x * 64;

    const __half* B1 = (e < NEXP) ? g_w1h + (size_t)e * INTER * DIM : g_ws1h;
    const __half* B3 = (e < NEXP) ? g_w3h + (size_t)e * INTER * DIM : g_ws3h;

    int tid = threadIdx.x;
    int wid = tid >> 5, lane = tid & 31;
    uint32_t tb = smem_u32(dsm);

    // loaders: A 4 chunks/thread (128 rows x 8 chunks), B1/B3 2 chunks/thread each
    uint32_t aoff[4]; const __half* asrc[4]; bool aval[4];
#pragma unroll
    for (int j = 0; j < 4; j++) {
        int idx = tid + j * 256;
        int row = idx >> 3, c = idx & 7;
        aoff[j] = swz(row, c);
        int r = m0 + row;
        aval[j] = (r < cnt);
        int tok = aval[j] ? g_pair_tok[e * T_TOK + r] : 0;
        asrc[j] = g_xh + (size_t)tok * DIM + c * 8;
    }
    uint32_t boff[2]; const __half *b1src[2], *b3src[2];
#pragma unroll
    for (int j = 0; j < 2; j++) {
        int idx = tid + j * 256;
        int row = idx >> 3, c = idx & 7;
        boff[j] = swz(row, c);
        b1src[j] = B1 + (size_t)(n0 + row) * DIM + c * 8;
        b3src[j] = B3 + (size_t)(n0 + row) * DIM + c * 8;
    }

    int wm = (wid & 1) * 64, wn = (wid >> 1) * 16;
    int lr = lane & 15, lc = lane >> 4;
    int g = lane >> 2, tg = lane & 3;

    int rA[4], rB;
#pragma unroll
    for (int mi = 0; mi < 4; mi++) rA[mi] = wm + mi * 16 + lr;
    rB = wn + lr;

    float acc1[4][2][4], acc3[4][2][4];
#pragma unroll
    for (int mi = 0; mi < 4; mi++)
#pragma unroll
        for (int ni = 0; ni < 2; ni++)
#pragma unroll
            for (int q = 0; q < 4; q++) { acc1[mi][ni][q] = 0.f; acc3[mi][ni][q] = 0.f; }

    const int NIT = DIM / 64;   // 32
#pragma unroll
    for (int st = 0; st < 2; st++) {
        uint32_t sb = tb + st * UPSTG;
#pragma unroll
        for (int j = 0; j < 4; j++) cp16(sb + aoff[j], asrc[j] + st * 64, aval[j]);
#pragma unroll
        for (int j = 0; j < 2; j++) {
            cp16(sb + 16384 + boff[j], b1src[j] + st * 64, true);
            cp16(sb + 24576 + boff[j], b3src[j] + st * 64, true);
        }
        CP_COMMIT();
    }

    uint32_t af[2][4][4], b1f[2][2][2], b3f[2][2][2];

    for (int it = 0; it < NIT; it++) {
        if (it < NIT - 1) CP_WAIT1(); else CP_WAIT0();
        __syncthreads();      // stage it ready AND stage it+2 free
        int pf = it + 2;
        if (pf < NIT) {
            uint32_t sb = tb + (pf % 3) * UPSTG;
#pragma unroll
            for (int j = 0; j < 4; j++) cp16(sb + aoff[j], asrc[j] + pf * 64, aval[j]);
#pragma unroll
            for (int j = 0; j < 2; j++) {
                cp16(sb + 16384 + boff[j], b1src[j] + pf * 64, true);
                cp16(sb + 24576 + boff[j], b3src[j] + pf * 64, true);
            }
            CP_COMMIT();
        }
        uint32_t sb = tb + (it % 3) * UPSTG;

        // load ks=0 fragments into buffer 0
#pragma unroll
        for (int mi = 0; mi < 4; mi++)
            LDSM4(af[0][mi][0], af[0][mi][1], af[0][mi][2], af[0][mi][3],
                  sb + swz(rA[mi], lc));
        {
            uint32_t r0, r1, r2, r3;
            LDSM4(r0, r1, r2, r3, sb + 16384 + swz(rB, lc));
            b1f[0][0][0] = r0; b1f[0][0][1] = r2; b1f[0][1][0] = r1; b1f[0][1][1] = r3;
            LDSM4(r0, r1, r2, r3, sb + 24576 + swz(rB, lc));
            b3f[0][0][0] = r0; b3f[0][0][1] = r2; b3f[0][1][0] = r1; b3f[0][1][1] = r3;
        }
#pragma unroll
        for (int ks = 0; ks < 4; ks++) {
            int cur = ks & 1, nxt = cur ^ 1;
            if (ks < 3) {
                int c = (ks + 1) * 2 + lc;
#pragma unroll
                for (int mi = 0; mi < 4; mi++)
                    LDSM4(af[nxt][mi][0], af[nxt][mi][1], af[nxt][mi][2], af[nxt][mi][3],
                          sb + swz(rA[mi], c));
                uint32_t r0, r1, r2, r3;
                LDSM4(r0, r1, r2, r3, sb + 16384 + swz(rB, c));
                b1f[nxt][0][0] = r0; b1f[nxt][0][1] = r2; b1f[nxt][1][0] = r1; b1f[nxt][1][1] = r3;
                LDSM4(r0, r1, r2, r3, sb + 24576 + swz(rB, c));
                b3f[nxt][0][0] = r0; b3f[nxt][0][1] = r2; b3f[nxt][1][0] = r1; b3f[nxt][1][1] = r3;
            }
#pragma unroll
            for (int mi = 0; mi < 4; mi++)
#pragma unroll
                for (int ni = 0; ni < 2; ni++) {
                    MMA16816(acc1[mi][ni], af[cur][mi], b1f[cur][ni]);
                    MMA16816(acc3[mi][ni], af[cur][mi], b3f[cur][ni]);
                }
        }
    }

    // epilogue: silu(h1)*h3 -> g_hidden (fp16)
#pragma unroll
    for (int mi = 0; mi < 4; mi++)
#pragma unroll
        for (int h = 0; h < 2; h++) {
            int m = wm + mi * 16 + g + h * 8;
            int slot = m0 + m;
            if (slot < cnt) {
                __half* dst = g_hidden + ((size_t)e * T_TOK + slot) * INTER + n0;
#pragma unroll
                for (int ni = 0; ni < 2; ni++) {
                    int n = wn + ni * 8 + 2 * tg;
                    float h1a = acc1[mi][ni][h * 2], h1b = acc1[mi][ni][h * 2 + 1];
                    float h3a = acc3[mi][ni][h * 2], h3b = acc3[mi][ni][h * 2 + 1];
                    float va = (h1a / (1.f + __expf(-h1a))) * h3a;
                    float vb = (h1b / (1.f + __expf(-h1b))) * h3b;
                    *(__half2*)&dst[n] = __floats2half2_rn(va, vb);
                }
            }
        }
}

// ================= fp16 down-proj: O = H W2^T, weight-folded store =================
// CTA tile M=128, N=128, BK=64. Stage: A[128x128B] @0, B[128x128B] @16384.
#define DNSTG 32768

__global__ __launch_bounds__(256, 2)
void down_kernel() {
    extern __shared__ __align__(1024) char dsm[];

    int e = blockIdx.z;
    int cnt = g_cnt[e];
    int m0 = blockIdx.y * 128;
    if (m0 >= cnt) return;
    int n0 = blockIdx.x * 128;

    const __half* B = (e < NEXP) ? g_w2h + (size_t)e * DIM * INTER : g_ws2h;

    int tid = threadIdx.x;
    int wid = tid >> 5, lane = tid & 31;
    uint32_t tb = smem_u32(dsm);

    uint32_t aoff[4]; const __half* asrc[4]; bool aval[4];
    const __half* bsrc[4];
#pragma unroll
    for (int j = 0; j < 4; j++) {
        int idx = tid + j * 256;
        int row = idx >> 3, c = idx & 7;
        aoff[j] = swz(row, c);
        int r = m0 + row;
        aval[j] = (r < cnt);
        asrc[j] = g_hidden + ((size_t)e * T_TOK + (aval[j] ? r : 0)) * INTER + c * 8;
        bsrc[j] = B + (size_t)(n0 + row) * INTER + c * 8;
    }

    int wm = (wid & 1) * 64, wn = (wid >> 1) * 32;
    int lr = lane & 15, lc = lane >> 4;
    int g = lane >> 2, tg = lane & 3;

    int rA[4], rB[2];
#pragma unroll
    for (int mi = 0; mi < 4; mi++) rA[mi] = wm + mi * 16 + lr;
#pragma unroll
    for (int bi = 0; bi < 2; bi++) rB[bi] = wn + bi * 16 + lr;

    float acc[4][4][4];
#pragma unroll
    for (int mi = 0; mi < 4; mi++)
#pragma unroll
        for (int ni = 0; ni < 4; ni++)
#pragma unroll
            for (int q = 0; q < 4; q++) acc[mi][ni][q] = 0.f;

    const int NIT = INTER / 64;   // 16
#pragma unroll
    for (int st = 0; st < 2; st++) {
        uint32_t sb = tb + st * DNSTG;
#pragma unroll
        for (int j = 0; j < 4; j++) {
            cp16(sb + aoff[j], asrc[j] + st * 64, aval[j]);
            cp16(sb + 16384 + aoff[j], bsrc[j] + st * 64, true);
        }
        CP_COMMIT();
    }

    uint32_t af[2][4][4], bf[2][4][2];

    for (int it = 0; it < NIT; it++) {
        if (it < NIT - 1) CP_WAIT1(); else CP_WAIT0();
        __syncthreads();
        int pf = it + 2;
        if (pf < NIT) {
            uint32_t sb = tb + (pf % 3) * DNSTG;
#pragma unroll
            for (int j = 0; j < 4; j++) {
                cp16(sb + aoff[j], asrc[j] + pf * 64, aval[j]);
                cp16(sb + 16384 + aoff[j], bsrc[j] + pf * 64, true);
            }
            CP_COMMIT();
        }
        uint32_t sb = tb + (it % 3) * DNSTG;

#pragma unroll
        for (int mi = 0; mi < 4; mi++)
            LDSM4(af[0][mi][0], af[0][mi][1], af[0][mi][2], af[0][mi][3],
                  sb + swz(rA[mi], lc));
#pragma unroll
        for (int bi = 0; bi < 2; bi++) {
            uint32_t r0, r1, r2, r3;
            LDSM4(r0, r1, r2, r3, sb + 16384 + swz(rB[bi], lc));
            bf[0][bi * 2][0] = r0; bf[0][bi * 2][1] = r2;
            bf[0][bi * 2 + 1][0] = r1; bf[0][bi * 2 + 1][1] = r3;
        }
#pragma unroll
        for (int ks = 0; ks < 4; ks++) {
            int cur = ks & 1, nxt = cur ^ 1;
            if (ks < 3) {
                int c = (ks + 1) * 2 + lc;
#pragma unroll
                for (int mi = 0; mi < 4; mi++)
                    LDSM4(af[nxt][mi][0], af[nxt][mi][1], af[nxt][mi][2], af[nxt][mi][3],
                          sb + swz(rA[mi], c));
#pragma unroll
                for (int bi = 0; bi < 2; bi++) {
                    uint32_t r0, r1, r2, r3;
                    LDSM4(r0, r1, r2, r3, sb + 16384 + swz(rB[bi], c));
                    bf[nxt][bi * 2][0] = r0; bf[nxt][bi * 2][1] = r2;
                    bf[nxt][bi * 2 + 1][0] = r1; bf[nxt][bi * 2 + 1][1] = r3;
                }
            }
#pragma unroll
            for (int mi = 0; mi < 4; mi++)
#pragma unroll
                for (int ni = 0; ni < 4; ni++)
                    MMA16816(acc[mi][ni], af[cur][mi], bf[cur][ni]);
        }
    }

    // epilogue: weight-fold + store to pairout
#pragma unroll
    for (int mi = 0; mi < 4; mi++)
#pragma unroll
        for (int h = 0; h < 2; h++) {
            int m = wm + mi * 16 + g + h * 8;
            int slot = m0 + m;
            if (slot < cnt) {
                float wv = g_pair_w[e * T_TOK + slot];
                float* dst = g_pairout + ((size_t)e * T_TOK + slot) * DIM + n0;
#pragma unroll
                for (int ni = 0; ni < 4; ni++) {
                    int n = wn + ni * 8 + 2 * tg;
                    float2 st;
                    st.x = acc[mi][ni][h * 2]     * wv;
                    st.y = acc[mi][ni][h * 2 + 1] * wv;
                    *(float2*)&dst[n] = st;
                }
            }
        }
}

// ---------------- combine (2 routed rows + shared row) ----------------
__global__ void combine_kernel(float* __restrict__ out) {
    int t = blockIdx.x;
    int r1 = g_tok_rows[2 * t], r2 = g_tok_rows[2 * t + 1];
    const float4* p1 = (const float4*)(g_pairout + (size_t)r1 * DIM);
    const float4* p2 = (const float4*)(g_pairout + (size_t)r2 * DIM);
    const float4* ps = (const float4*)(g_pairout + ((size_t)NEXP * T_TOK + t) * DIM);
    float4* o = (float4*)(out + (size_t)t * DIM);
#pragma unroll
    for (int i = threadIdx.x; i < DIM / 4; i += 256) {
        float4 a = p1[i], b = p2[i], c = ps[i];
        o[i] = make_float4(a.x + b.x + c.x, a.y + b.y + c.y,
                           a.z + b.z + c.z, a.w + b.w + c.w);
    }
}

// ---------------- launch ----------------
extern "C" void kernel_launch(void* const* d_in, const int* in_sizes, int n_in,
                              void* d_out, int out_size) {
    const float* x      = (const float*)d_in[0];
    const float* gate_w = (const float*)d_in[1];
    const float* w1     = (const float*)d_in[2];
    const float* w2     = (const float*)d_in[3];
    const float* w3     = (const float*)d_in[4];
    const float* ws1    = (const float*)d_in[5];
    const float* ws2    = (const float*)d_in[6];
    const float* ws3    = (const float*)d_in[7];
    float* out = (float*)d_out;

    cudaFuncSetAttribute(up_kernel,   cudaFuncAttributeMaxDynamicSharedMemorySize, 3 * UPSTG);
    cudaFuncSetAttribute(down_kernel, cudaFuncAttributeMaxDynamicSharedMemorySize, 3 * DNSTG);

    __half* w1h;  cudaGetSymbolAddress((void**)&w1h,  g_w1h);
    __half* w3h;  cudaGetSymbolAddress((void**)&w3h,  g_w3h);
    __half* w2h;  cudaGetSymbolAddress((void**)&w2h,  g_w2h);
    __half* ws1h; cudaGetSymbolAddress((void**)&ws1h, g_ws1h);
    __half* ws3h; cudaGetSymbolAddress((void**)&ws3h, g_ws3h);
    __half* ws2h; cudaGetSymbolAddress((void**)&ws2h, g_ws2h);

    Seg s0 = { (const float4*)w1,  (uint2*)w1h,  NEXP * INTER * DIM / 4 };
    Seg s1 = { (const float4*)w3,  (uint2*)w3h,  NEXP * INTER * DIM / 4 };
    Seg s2 = { (const float4*)w2,  (uint2*)w2h,  NEXP * DIM * INTER / 4 };
    Seg s3 = { (const float4*)ws1, (uint2*)ws1h, INTER * DIM / 4 };
    Seg s4 = { (const float4*)ws3, (uint2*)ws3h, INTER * DIM / 4 };
    Seg s5 = { (const float4*)ws2, (uint2*)ws2h, DIM * INTER / 4 };
    convert_all_kernel<<<2048, 256>>>(s0, s1, s2, s3, s4, s5);

    gate_kernel<<<T_TOK, 256>>>(x, gate_w);
    {
        dim3 grid(INTER / 64, T_TOK / 128, NE);
        up_kernel<<<grid, 256, 3 * UPSTG>>>();
    }
    {
        dim3 grid(DIM / 128, T_TOK / 128, NE);
        down_kernel<<<grid, 256, 3 * DNSTG>>>();
    }
    combine_kernel<<<T_TOK, 256>>>(out);
}

// round 11
// speedup vs baseline: 2.3385x; 1.0074x over previous
#include <cuda_runtime.h>
#include <cuda_fp16.h>
#include <stdint.h>
#include <math.h>

#define T_TOK 4096
#define DIM   2048
#define INTER 1024
#define NEXP  8
#define NE    9      // 8 routed + 1 shared pseudo-expert

// ---------------- scratch (device globals; no allocation allowed) ----------------
__device__ __half g_hidden [(size_t)NE * T_TOK * INTER];  // post-SwiGLU hidden (fp16)
__device__ __half g_pairout[(size_t)NE * T_TOK * DIM];    // weighted expert outputs (fp16)
__device__ __half g_xh     [(size_t)T_TOK * DIM];         // fp16 activations
__device__ __half g_w1h [(size_t)NEXP * INTER * DIM];
__device__ __half g_w3h [(size_t)NEXP * INTER * DIM];
__device__ __half g_w2h [(size_t)NEXP * DIM * INTER];
__device__ __half g_ws1h[(size_t)INTER * DIM];
__device__ __half g_ws3h[(size_t)INTER * DIM];
__device__ __half g_ws2h[(size_t)DIM * INTER];
__device__ int    g_pair_tok[NE * T_TOK];
__device__ float  g_pair_w [NE * T_TOK];
__device__ int    g_tok_rows[T_TOK * 2];
__device__ int    g_cnt[NE];

// ---------------- PTX helpers ----------------
__device__ __forceinline__ uint32_t smem_u32(const void* p) {
    return (uint32_t)__cvta_generic_to_shared(p);
}
__device__ __forceinline__ void cp16(uint32_t dst, const void* src, bool valid) {
    int sz = valid ? 16 : 0;
    asm volatile("cp.async.cg.shared.global [%0], [%1], 16, %2;\n"
                 :: "r"(dst), "l"(src), "r"(sz));
}
#define CP_COMMIT() asm volatile("cp.async.commit_group;\n")
#define CP_WAIT1()  asm volatile("cp.async.wait_group 1;\n")
#define CP_WAIT0()  asm volatile("cp.async.wait_group 0;\n")

#define LDSM4(r0, r1, r2, r3, a) \
    asm volatile("ldmatrix.sync.aligned.m8n8.x4.shared.b16 {%0,%1,%2,%3}, [%4];" \
                 : "=r"(r0), "=r"(r1), "=r"(r2), "=r"(r3) : "r"(a))

#define MMA16816(c, a, b) \
    asm volatile("mma.sync.aligned.m16n8k16.row.col.f32.f16.f16.f32 " \
                 "{%0,%1,%2,%3},{%4,%5,%6,%7},{%8,%9},{%0,%1,%2,%3};" \
                 : "+f"((c)[0]), "+f"((c)[1]), "+f"((c)[2]), "+f"((c)[3]) \
                 : "r"((a)[0]), "r"((a)[1]), "r"((a)[2]), "r"((a)[3]), \
                   "r"((b)[0]), "r"((b)[1]))

// SW128 swizzle for 128B rows: 16B chunk index XOR row%8 -> conflict-free LDSM + cp.async
__device__ __forceinline__ uint32_t swz(uint32_t row, uint32_t c) {
    return row * 128 + ((c ^ (row & 7)) << 4);
}

// ---------------- merged convert (+init): f32 -> f16 over 6 segments ----------------
struct Seg { const float4* src; uint2* dst; int n4; };

__global__ void convert_all_kernel(Seg s0, Seg s1, Seg s2, Seg s3, Seg s4, Seg s5) {
    if (blockIdx.x == 0 && threadIdx.x < NE)
        g_cnt[threadIdx.x] = (threadIdx.x == NEXP) ? T_TOK : 0;
    Seg segs[6] = { s0, s1, s2, s3, s4, s5 };
    int stride = gridDim.x * blockDim.x;
    int tid = blockIdx.x * blockDim.x + threadIdx.x;
#pragma unroll
    for (int s = 0; s < 6; s++) {
        const float4* src = segs[s].src;
        uint2* dst = segs[s].dst;
        int n4 = segs[s].n4;
        for (int i = tid; i < n4; i += stride) {
            float4 v = src[i];
            __half2 a = __floats2half2_rn(v.x, v.y);
            __half2 b = __floats2half2_rn(v.z, v.w);
            uint2 o;
            o.x = *(uint32_t*)&a;
            o.y = *(uint32_t*)&b;
            dst[i] = o;
        }
    }
}

// ---------------- gate: softmax + top2 + list build + fp16 x copy ----------------
__global__ void gate_kernel(const float* __restrict__ x,
                            const float* __restrict__ gw) {
    int t = blockIdx.x;
    const float* xr = x + (size_t)t * DIM;
    __half* xo = g_xh + (size_t)t * DIM;

    float acc[NEXP];
#pragma unroll
    for (int e = 0; e < NEXP; e++) acc[e] = 0.f;
    for (int d = threadIdx.x; d < DIM; d += 256) {
        float xv = xr[d];
        xo[d] = __float2half_rn(xv);
#pragma unroll
        for (int e = 0; e < NEXP; e++) acc[e] += xv * gw[e * DIM + d];
    }
#pragma unroll
    for (int off = 16; off > 0; off >>= 1) {
#pragma unroll
        for (int e = 0; e < NEXP; e++)
            acc[e] += __shfl_down_sync(0xffffffffu, acc[e], off);
    }
    __shared__ float sw[8][NEXP];
    int warp = threadIdx.x >> 5, lane = threadIdx.x & 31;
    if (lane == 0) {
#pragma unroll
        for (int e = 0; e < NEXP; e++) sw[warp][e] = acc[e];
    }
    __syncthreads();
    if (threadIdx.x == 0) {
        float lg[NEXP];
#pragma unroll
        for (int e = 0; e < NEXP; e++) {
            float s = 0.f;
#pragma unroll
            for (int w = 0; w < 8; w++) s += sw[w][e];
            lg[e] = s;
        }
        float mx = lg[0];
#pragma unroll
        for (int e = 1; e < NEXP; e++) mx = fmaxf(mx, lg[e]);
        float p[NEXP]; float sum = 0.f;
#pragma unroll
        for (int e = 0; e < NEXP; e++) { p[e] = expf(lg[e] - mx); sum += p[e]; }
        float inv = 1.f / sum;
#pragma unroll
        for (int e = 0; e < NEXP; e++) p[e] *= inv;
        int i1 = 0;
#pragma unroll
        for (int e = 1; e < NEXP; e++) if (p[e] > p[i1]) i1 = e;
        int i2 = (i1 == 0) ? 1 : 0;
#pragma unroll
        for (int e = 0; e < NEXP; e++) if (e != i1 && p[e] > p[i2]) i2 = e;

        int s1 = atomicAdd(&g_cnt[i1], 1);
        g_pair_tok[i1 * T_TOK + s1] = t;
        g_pair_w [i1 * T_TOK + s1] = p[i1];
        int s2 = atomicAdd(&g_cnt[i2], 1);
        g_pair_tok[i2 * T_TOK + s2] = t;
        g_pair_w [i2 * T_TOK + s2] = p[i2];
        g_tok_rows[2 * t]     = i1 * T_TOK + s1;
        g_tok_rows[2 * t + 1] = i2 * T_TOK + s2;
        g_pair_tok[NEXP * T_TOK + t] = t;
        g_pair_w [NEXP * T_TOK + t] = 1.0f;
    }
}

// ================= fp16 up-proj: H = silu(X W1^T) * (X W3^T) =================
// CTA tile M=128, N=64 dual-matrix. BK=64 halfs (128B SW128 rows), 3-stage x 32KB.
#define UPSTG 32768

__global__ __launch_bounds__(256, 2)
void up_kernel() {
    extern __shared__ __align__(1024) char dsm[];

    int e = blockIdx.z;
    int cnt = g_cnt[e];
    int m0 = blockIdx.y * 128;
    if (m0 >= cnt) return;
    int n0 = blockIdx.x * 64;

    const __half* B1 = (e < NEXP) ? g_w1h + (size_t)e * INTER * DIM : g_ws1h;
    const __half* B3 = (e < NEXP) ? g_w3h + (size_t)e * INTER * DIM : g_ws3h;

    int tid = threadIdx.x;
    int wid = tid >> 5, lane = tid & 31;
    uint32_t tb = smem_u32(dsm);

    uint32_t aoff[4]; const __half* asrc[4]; bool aval[4];
#pragma unroll
    for (int j = 0; j < 4; j++) {
        int idx = tid + j * 256;
        int row = idx >> 3, c = idx & 7;
        aoff[j] = swz(row, c);
        int r = m0 + row;
        aval[j] = (r < cnt);
        int tok = aval[j] ? g_pair_tok[e * T_TOK + r] : 0;
        asrc[j] = g_xh + (size_t)tok * DIM + c * 8;
    }
    uint32_t boff[2]; const __half *b1src[2], *b3src[2];
#pragma unroll
    for (int j = 0; j < 2; j++) {
        int idx = tid + j * 256;
        int row = idx >> 3, c = idx & 7;
        boff[j] = swz(row, c);
        b1src[j] = B1 + (size_t)(n0 + row) * DIM + c * 8;
        b3src[j] = B3 + (size_t)(n0 + row) * DIM + c * 8;
    }

    int wm = (wid & 1) * 64, wn = (wid >> 1) * 16;
    int lr = lane & 15, lc = lane >> 4;
    int g = lane >> 2, tg = lane & 3;

    int rA[4], rB;
#pragma unroll
    for (int mi = 0; mi < 4; mi++) rA[mi] = wm + mi * 16 + lr;
    rB = wn + lr;

    float acc1[4][2][4], acc3[4][2][4];
#pragma unroll
    for (int mi = 0; mi < 4; mi++)
#pragma unroll
        for (int ni = 0; ni < 2; ni++)
#pragma unroll
            for (int q = 0; q < 4; q++) { acc1[mi][ni][q] = 0.f; acc3[mi][ni][q] = 0.f; }

    const int NIT = DIM / 64;   // 32
#pragma unroll
    for (int st = 0; st < 2; st++) {
        uint32_t sb = tb + st * UPSTG;
#pragma unroll
        for (int j = 0; j < 4; j++) cp16(sb + aoff[j], asrc[j] + st * 64, aval[j]);
#pragma unroll
        for (int j = 0; j < 2; j++) {
            cp16(sb + 16384 + boff[j], b1src[j] + st * 64, true);
            cp16(sb + 24576 + boff[j], b3src[j] + st * 64, true);
        }
        CP_COMMIT();
    }

    uint32_t af[2][4][4], b1f[2][2][2], b3f[2][2][2];

    // one ring iteration; sb/psb computed from LITERAL stage ids at call sites
    auto iter = [&](int it, uint32_t sb, uint32_t psb) {
        if (it < NIT - 1) CP_WAIT1(); else CP_WAIT0();
        __syncthreads();
        int pf = it + 2;
        if (pf < NIT) {
#pragma unroll
            for (int j = 0; j < 4; j++) cp16(psb + aoff[j], asrc[j] + pf * 64, aval[j]);
#pragma unroll
            for (int j = 0; j < 2; j++) {
                cp16(psb + 16384 + boff[j], b1src[j] + pf * 64, true);
                cp16(psb + 24576 + boff[j], b3src[j] + pf * 64, true);
            }
            CP_COMMIT();
        }
#pragma unroll
        for (int mi = 0; mi < 4; mi++)
            LDSM4(af[0][mi][0], af[0][mi][1], af[0][mi][2], af[0][mi][3],
                  sb + swz(rA[mi], lc));
        {
            uint32_t r0, r1, r2, r3;
            LDSM4(r0, r1, r2, r3, sb + 16384 + swz(rB, lc));
            b1f[0][0][0] = r0; b1f[0][0][1] = r2; b1f[0][1][0] = r1; b1f[0][1][1] = r3;
            LDSM4(r0, r1, r2, r3, sb + 24576 + swz(rB, lc));
            b3f[0][0][0] = r0; b3f[0][0][1] = r2; b3f[0][1][0] = r1; b3f[0][1][1] = r3;
        }
#pragma unroll
        for (int ks = 0; ks < 4; ks++) {
            int cur = ks & 1, nxt = cur ^ 1;
            if (ks < 3) {
                int c = (ks + 1) * 2 + lc;
#pragma unroll
                for (int mi = 0; mi < 4; mi++)
                    LDSM4(af[nxt][mi][0], af[nxt][mi][1], af[nxt][mi][2], af[nxt][mi][3],
                          sb + swz(rA[mi], c));
                uint32_t r0, r1, r2, r3;
                LDSM4(r0, r1, r2, r3, sb + 16384 + swz(rB, c));
                b1f[nxt][0][0] = r0; b1f[nxt][0][1] = r2; b1f[nxt][1][0] = r1; b1f[nxt][1][1] = r3;
                LDSM4(r0, r1, r2, r3, sb + 24576 + swz(rB, c));
                b3f[nxt][0][0] = r0; b3f[nxt][0][1] = r2; b3f[nxt][1][0] = r1; b3f[nxt][1][1] = r3;
            }
#pragma unroll
            for (int mi = 0; mi < 4; mi++)
#pragma unroll
                for (int ni = 0; ni < 2; ni++) {
                    MMA16816(acc1[mi][ni], af[cur][mi], b1f[cur][ni]);
                    MMA16816(acc3[mi][ni], af[cur][mi], b3f[cur][ni]);
                }
        }
    };

    for (int base = 0; base < NIT; base += 3) {
        iter(base,     tb,             tb + 2 * UPSTG);
        if (base + 1 < NIT) iter(base + 1, tb + UPSTG,     tb);
        if (base + 2 < NIT) iter(base + 2, tb + 2 * UPSTG, tb + UPSTG);
    }

    // epilogue: silu(h1)*h3 -> g_hidden (fp16)
#pragma unroll
    for (int mi = 0; mi < 4; mi++)
#pragma unroll
        for (int h = 0; h < 2; h++) {
            int m = wm + mi * 16 + g + h * 8;
            int slot = m0 + m;
            if (slot < cnt) {
                __half* dst = g_hidden + ((size_t)e * T_TOK + slot) * INTER + n0;
#pragma unroll
                for (int ni = 0; ni < 2; ni++) {
                    int n = wn + ni * 8 + 2 * tg;
                    float h1a = acc1[mi][ni][h * 2], h1b = acc1[mi][ni][h * 2 + 1];
                    float h3a = acc3[mi][ni][h * 2], h3b = acc3[mi][ni][h * 2 + 1];
                    float va = (h1a / (1.f + __expf(-h1a))) * h3a;
                    float vb = (h1b / (1.f + __expf(-h1b))) * h3b;
                    *(__half2*)&dst[n] = __floats2half2_rn(va, vb);
                }
            }
        }
}

// ================= fp16 down-proj: O = H W2^T, weight-folded fp16 store =================
#define DNSTG 32768

__global__ __launch_bounds__(256, 2)
void down_kernel() {
    extern __shared__ __align__(1024) char dsm[];

    int e = blockIdx.z;
    int cnt = g_cnt[e];
    int m0 = blockIdx.y * 128;
    if (m0 >= cnt) return;
    int n0 = blockIdx.x * 128;

    const __half* B = (e < NEXP) ? g_w2h + (size_t)e * DIM * INTER : g_ws2h;

    int tid = threadIdx.x;
    int wid = tid >> 5, lane = tid & 31;
    uint32_t tb = smem_u32(dsm);

    uint32_t aoff[4]; const __half* asrc[4]; bool aval[4];
    const __half* bsrc[4];
#pragma unroll
    for (int j = 0; j < 4; j++) {
        int idx = tid + j * 256;
        int row = idx >> 3, c = idx & 7;
        aoff[j] = swz(row, c);
        int r = m0 + row;
        aval[j] = (r < cnt);
        asrc[j] = g_hidden + ((size_t)e * T_TOK + (aval[j] ? r : 0)) * INTER + c * 8;
        bsrc[j] = B + (size_t)(n0 + row) * INTER + c * 8;
    }

    int wm = (wid & 1) * 64, wn = (wid >> 1) * 32;
    int lr = lane & 15, lc = lane >> 4;
    int g = lane >> 2, tg = lane & 3;

    int rA[4], rB[2];
#pragma unroll
    for (int mi = 0; mi < 4; mi++) rA[mi] = wm + mi * 16 + lr;
#pragma unroll
    for (int bi = 0; bi < 2; bi++) rB[bi] = wn + bi * 16 + lr;

    float acc[4][4][4];
#pragma unroll
    for (int mi = 0; mi < 4; mi++)
#pragma unroll
        for (int ni = 0; ni < 4; ni++)
#pragma unroll
            for (int q = 0; q < 4; q++) acc[mi][ni][q] = 0.f;

    const int NIT = INTER / 64;   // 16
#pragma unroll
    for (int st = 0; st < 2; st++) {
        uint32_t sb = tb + st * DNSTG;
#pragma unroll
        for (int j = 0; j < 4; j++) {
            cp16(sb + aoff[j], asrc[j] + st * 64, aval[j]);
            cp16(sb + 16384 + aoff[j], bsrc[j] + st * 64, true);
        }
        CP_COMMIT();
    }

    uint32_t af[2][4][4], bf[2][4][2];

    auto iter = [&](int it, uint32_t sb, uint32_t psb) {
        if (it < NIT - 1) CP_WAIT1(); else CP_WAIT0();
        __syncthreads();
        int pf = it + 2;
        if (pf < NIT) {
#pragma unroll
            for (int j = 0; j < 4; j++) {
                cp16(psb + aoff[j], asrc[j] + pf * 64, aval[j]);
                cp16(psb + 16384 + aoff[j], bsrc[j] + pf * 64, true);
            }
            CP_COMMIT();
        }
#pragma unroll
        for (int mi = 0; mi < 4; mi++)
            LDSM4(af[0][mi][0], af[0][mi][1], af[0][mi][2], af[0][mi][3],
                  sb + swz(rA[mi], lc));
#pragma unroll
        for (int bi = 0; bi < 2; bi++) {
            uint32_t r0, r1, r2, r3;
            LDSM4(r0, r1, r2, r3, sb + 16384 + swz(rB[bi], lc));
            bf[0][bi * 2][0] = r0; bf[0][bi * 2][1] = r2;
            bf[0][bi * 2 + 1][0] = r1; bf[0][bi * 2 + 1][1] = r3;
        }
#pragma unroll
        for (int ks = 0; ks < 4; ks++) {
            int cur = ks & 1, nxt = cur ^ 1;
            if (ks < 3) {
                int c = (ks + 1) * 2 + lc;
#pragma unroll
                for (int mi = 0; mi < 4; mi++)
                    LDSM4(af[nxt][mi][0], af[nxt][mi][1], af[nxt][mi][2], af[nxt][mi][3],
                          sb + swz(rA[mi], c));
#pragma unroll
                for (int bi = 0; bi < 2; bi++) {
                    uint32_t r0, r1, r2, r3;
                    LDSM4(r0, r1, r2, r3, sb + 16384 + swz(rB[bi], c));
                    bf[nxt][bi * 2][0] = r0; bf[nxt][bi * 2][1] = r2;
                    bf[nxt][bi * 2 + 1][0] = r1; bf[nxt][bi * 2 + 1][1] = r3;
                }
            }
#pragma unroll
            for (int mi = 0; mi < 4; mi++)
#pragma unroll
                for (int ni = 0; ni < 4; ni++)
                    MMA16816(acc[mi][ni], af[cur][mi], bf[cur][ni]);
        }
    };

    for (int base = 0; base < NIT; base += 3) {
        iter(base,     tb,             tb + 2 * DNSTG);
        if (base + 1 < NIT) iter(base + 1, tb + DNSTG,     tb);
        if (base + 2 < NIT) iter(base + 2, tb + 2 * DNSTG, tb + DNSTG);
    }

    // epilogue: weight-fold + fp16 store to pairout
#pragma unroll
    for (int mi = 0; mi < 4; mi++)
#pragma unroll
        for (int h = 0; h < 2; h++) {
            int m = wm + mi * 16 + g + h * 8;
            int slot = m0 + m;
            if (slot < cnt) {
                float wv = g_pair_w[e * T_TOK + slot];
                __half* dst = g_pairout + ((size_t)e * T_TOK + slot) * DIM + n0;
#pragma unroll
                for (int ni = 0; ni < 4; ni++) {
                    int n = wn + ni * 8 + 2 * tg;
                    *(__half2*)&dst[n] = __floats2half2_rn(acc[mi][ni][h * 2] * wv,
                                                           acc[mi][ni][h * 2 + 1] * wv);
                }
            }
        }
}

// ---------------- combine (2 routed rows + shared row, fp16 in / fp32 out) ----------------
__global__ void combine_kernel(float* __restrict__ out) {
    int t = blockIdx.x;
    int r1 = g_tok_rows[2 * t], r2 = g_tok_rows[2 * t + 1];
    const uint2* p1 = (const uint2*)(g_pairout + (size_t)r1 * DIM);
    const uint2* p2 = (const uint2*)(g_pairout + (size_t)r2 * DIM);
    const uint2* ps = (const uint2*)(g_pairout + ((size_t)NEXP * T_TOK + t) * DIM);
    float4* o = (float4*)(out + (size_t)t * DIM);
    for (int i = threadIdx.x; i < DIM / 4; i += 256) {
        uint2 u1 = p1[i], u2 = p2[i], us = ps[i];
        float2 a0 = __half22float2(*(__half2*)&u1.x);
        float2 a1 = __half22float2(*(__half2*)&u1.y);
        float2 b0 = __half22float2(*(__half2*)&u2.x);
        float2 b1 = __half22float2(*(__half2*)&u2.y);
        float2 c0 = __half22float2(*(__half2*)&us.x);
        float2 c1 = __half22float2(*(__half2*)&us.y);
        o[i] = make_float4(a0.x + b0.x + c0.x, a0.y + b0.y + c0.y,
                           a1.x + b1.x + c1.x, a1.y + b1.y + c1.y);
    }
}

// ---------------- launch ----------------
extern "C" void kernel_launch(void* const* d_in, const int* in_sizes, int n_in,
                              void* d_out, int out_size) {
    const float* x      = (const float*)d_in[0];
    const float* gate_w = (const float*)d_in[1];
    const float* w1     = (const float*)d_in[2];
    const float* w2     = (const float*)d_in[3];
    const float* w3     = (const float*)d_in[4];
    const float* ws1    = (const float*)d_in[5];
    const float* ws2    = (const float*)d_in[6];
    const float* ws3    = (const float*)d_in[7];
    float* out = (float*)d_out;

    cudaFuncSetAttribute(up_kernel,   cudaFuncAttributeMaxDynamicSharedMemorySize, 3 * UPSTG);
    cudaFuncSetAttribute(down_kernel, cudaFuncAttributeMaxDynamicSharedMemorySize, 3 * DNSTG);

    __half* w1h;  cudaGetSymbolAddress((void**)&w1h,  g_w1h);
    __half* w3h;  cudaGetSymbolAddress((void**)&w3h,  g_w3h);
    __half* w2h;  cudaGetSymbolAddress((void**)&w2h,  g_w2h);
    __half* ws1h; cudaGetSymbolAddress((void**)&ws1h, g_ws1h);
    __half* ws3h; cudaGetSymbolAddress((void**)&ws3h, g_ws3h);
    __half* ws2h; cudaGetSymbolAddress((void**)&ws2h, g_ws2h);

    Seg s0 = { (const float4*)w1,  (uint2*)w1h,  NEXP * INTER * DIM / 4 };
    Seg s1 = { (const float4*)w3,  (uint2*)w3h,  NEXP * INTER * DIM / 4 };
    Seg s2 = { (const float4*)w2,  (uint2*)w2h,  NEXP * DIM * INTER / 4 };
    Seg s3 = { (const float4*)ws1, (uint2*)ws1h, INTER * DIM / 4 };
    Seg s4 = { (const float4*)ws3, (uint2*)ws3h, INTER * DIM / 4 };
    Seg s5 = { (const float4*)ws2, (uint2*)ws2h, DIM * INTER / 4 };
    convert_all_kernel<<<2048, 256>>>(s0, s1, s2, s3, s4, s5);

    gate_kernel<<<T_TOK, 256>>>(x, gate_w);
    {
        dim3 grid(INTER / 64, T_TOK / 128, NE);
        up_kernel<<<grid, 256, 3 * UPSTG>>>();
    }
    {
        dim3 grid(DIM / 128, T_TOK / 128, NE);
        down_kernel<<<grid, 256, 3 * DNSTG>>>();
    }
    combine_kernel<<<T_TOK, 256>>>(out);
}